// round 1
// baseline (speedup 1.0000x reference)
#include <cuda_runtime.h>
#include <math.h>

#define B_ 4
#define T_ 1024
#define D_ 1024
#define H_ 16
#define HS_ 64
#define BT_ (B_*T_)
#define DECAY_C (-0.606531f)

// ---------------- scratch (device globals; no allocation allowed) ----------------
__device__ float g_r  [BT_*D_];
__device__ float g_wl [BT_*D_];   // wl, then wdec in place
__device__ float g_k  [BT_*D_];
__device__ float g_v  [BT_*D_];
__device__ float g_a  [BT_*D_];
__device__ float g_g  [BT_*D_];
__device__ float g_at [BT_*D_];   // -kk (normalized)
__device__ float g_bt [BT_*D_];   // kk * a
__device__ float g_hv [BT_*D_];   // sigmoid v-lora gate
__device__ float g_hw [BT_*64];
__device__ float g_ha [BT_*64];
__device__ float g_hv1[BT_*32];
__device__ float g_hg [BT_*128];
__device__ float g_rks[BT_*H_];
__device__ float g_y  [BT_*D_];
__device__ float g_z  [BT_*D_];
__device__ float g_ds [B_*H_*HS_*HS_];  // dummy state sink if out_size too small

// ---------------- generic fp32 tiled GEMM with fused mix / bias / activation ----
// MIX: A[m][k] = cur + lam[k]*(prev - cur)   (token-shift mixing fused into load)
// ACT: 0 none, 1 tanh, 2 sigmoid.  BIAS: add bias[col].
template<int BM,int BN,int BK,int TM,int TN,int MIX,int ACT,int BIAS>
__launch_bounds__(256)
__global__ void sgemm(const float* __restrict__ A,
                      const float* __restrict__ cur, const float* __restrict__ prev,
                      const float* __restrict__ lam,
                      const float* __restrict__ Bm, const float* __restrict__ bias,
                      float* __restrict__ C, int M, int N, int K)
{
    constexpr int THREADS = (BM/TM)*(BN/TN);
    static_assert(THREADS == 256, "block must be 256 threads");
    __shared__ float As[BK][BM];
    __shared__ float Bs[BK][BN];
    const int tid  = threadIdx.x;
    const int brow = blockIdx.y * BM;
    const int bcol = blockIdx.x * BN;
    const int tcol = (tid % (BN/TN)) * TN;
    const int trow = (tid / (BN/TN)) * TM;
    float acc[TM][TN];
    #pragma unroll
    for (int i = 0; i < TM; i++)
        #pragma unroll
        for (int j = 0; j < TN; j++) acc[i][j] = 0.f;

    for (int k0 = 0; k0 < K; k0 += BK) {
        #pragma unroll
        for (int x = tid; x < BM*BK; x += THREADS) {
            int m = x / BK, kk = x % BK;
            int g = (brow + m) * K + k0 + kk;
            float val;
            if (MIX) { float c = cur[g]; val = c + lam[k0+kk] * (prev[g] - c); }
            else     { val = A[g]; }
            As[kk][m] = val;
        }
        #pragma unroll
        for (int x = tid; x < BK*BN; x += THREADS) {
            int kk = x / BN, n = x % BN;
            Bs[kk][n] = Bm[(k0+kk)*N + bcol + n];
        }
        __syncthreads();
        #pragma unroll
        for (int kk = 0; kk < BK; kk++) {
            float av[TM], bv[TN];
            #pragma unroll
            for (int i = 0; i < TM; i++) av[i] = As[kk][trow+i];
            #pragma unroll
            for (int j = 0; j < TN; j++) bv[j] = Bs[kk][tcol+j];
            #pragma unroll
            for (int i = 0; i < TM; i++)
                #pragma unroll
                for (int j = 0; j < TN; j++) acc[i][j] += av[i] * bv[j];
        }
        __syncthreads();
    }
    #pragma unroll
    for (int i = 0; i < TM; i++)
        #pragma unroll
        for (int j = 0; j < TN; j++) {
            float v2 = acc[i][j];
            if (BIAS) v2 += bias[bcol + tcol + j];
            if (ACT == 1) v2 = tanhf(v2);
            else if (ACT == 2) v2 = 1.f / (1.f + expf(-v2));
            C[(brow+trow+i)*N + bcol+tcol+j] = v2;
        }
}

// ---------------- post: kk-norm, k/v modification, decay, rk_sum, at/bt --------
__launch_bounds__(512)
__global__ void post_kernel(float* __restrict__ K_, float* __restrict__ V_,
    float* __restrict__ WL, const float* __restrict__ A_, const float* __restrict__ R_,
    const float* __restrict__ HV, const float* __restrict__ vfirst,
    const float* __restrict__ kkv, const float* __restrict__ kav, const float* __restrict__ rkv,
    float* __restrict__ AT, float* __restrict__ BTt, float* __restrict__ RKS)
{
    int bt = blockIdx.x;
    int h = threadIdx.x >> 5, lane = threadIdx.x & 31;
    int base = bt * D_ + h * HS_;
    int ce0 = h*HS_ + lane, ce1 = ce0 + 32;
    int i0 = base + lane, i1 = i0 + 32;

    float k0 = K_[i0], k1 = K_[i1];
    float kk0 = k0 * kkv[ce0], kk1 = k1 * kkv[ce1];
    float n2 = kk0*kk0 + kk1*kk1;
    #pragma unroll
    for (int o = 16; o; o >>= 1) n2 += __shfl_xor_sync(0xffffffffu, n2, o);
    float inv = rsqrtf(n2);
    kk0 *= inv; kk1 *= inv;

    float a0 = A_[i0], a1 = A_[i1];
    AT[i0] = -kk0;      AT[i1] = -kk1;
    BTt[i0] = kk0 * a0; BTt[i1] = kk1 * a1;

    k0 *= 1.f + (a0 - 1.f) * kav[ce0];
    k1 *= 1.f + (a1 - 1.f) * kav[ce1];
    K_[i0] = k0; K_[i1] = k1;

    float v0 = V_[i0], v1 = V_[i1];
    float hg0 = HV[i0], hg1 = HV[i1];
    v0 += (vfirst[i0] - v0) * hg0;
    v1 += (vfirst[i1] - v1) * hg1;
    V_[i0] = v0; V_[i1] = v1;

    float w0 = WL[i0], w1 = WL[i1];
    WL[i0] = expf(DECAY_C / (1.f + expf(-w0)));
    WL[i1] = expf(DECAY_C / (1.f + expf(-w1)));

    float rs = R_[i0]*k0*rkv[ce0] + R_[i1]*k1*rkv[ce1];
    #pragma unroll
    for (int o = 16; o; o >>= 1) rs += __shfl_xor_sync(0xffffffffu, rs, o);
    if (lane == 0) RKS[bt*H_ + h] = rs;
}

// ---------------- sequential scan over T ---------------------------------------
// block = (b, h, v-half): 128 blocks. thread = kg*32 + vl, kg in [0,8) (8 k's each),
// vl in [0,32). Warp-uniform kg => broadcast LDS of per-k vectors.
#define LOAD8(dst, ptr) do { \
    float4 u0 = *(const float4*)(ptr); float4 u1 = *(const float4*)((ptr)+4); \
    dst[0]=u0.x; dst[1]=u0.y; dst[2]=u0.z; dst[3]=u0.w; \
    dst[4]=u1.x; dst[5]=u1.y; dst[6]=u1.z; dst[7]=u1.w; } while(0)

__launch_bounds__(256)
__global__ void scan_kernel(const float* __restrict__ R_, const float* __restrict__ W_,
    const float* __restrict__ K_, const float* __restrict__ V_,
    const float* __restrict__ AT, const float* __restrict__ BTt,
    float* __restrict__ Y, float* __restrict__ S)
{
    __shared__ float4 vbuf[2][88];       // at(16) w(16) bt(16) k(16) r(16) v(8) float4s
    __shared__ float redA[8][32];
    __shared__ float redY[8][32];
    int bid = blockIdx.x;                // 0..127
    int b = bid >> 5; int rem = bid & 31; int h = rem >> 1; int half = rem & 1;
    int tid = threadIdx.x;
    int kg = tid >> 5, vl = tid & 31;
    int kb = kg * 8;

    const float* msrc = nullptr;
    if (tid < 88) {
        const float* bp; int inner;
        if (tid < 80) {
            int arr = tid / 16, q = tid % 16;
            bp = (arr==0) ? AT : (arr==1) ? W_ : (arr==2) ? BTt : (arr==3) ? K_ : R_;
            inner = q * 4;
        } else {
            bp = V_; inner = half*32 + (tid - 80) * 4;
        }
        msrc = bp + h*HS_ + inner;
    }

    float s[8];
    #pragma unroll
    for (int i = 0; i < 8; i++) s[i] = 0.f;

    size_t row0 = (size_t)b * T_ * D_;
    if (tid < 88) vbuf[0][tid] = *(const float4*)(msrc + row0);
    __syncthreads();

    for (int t = 0; t < T_; t++) {
        int cb = t & 1;
        if (tid < 88 && t + 1 < T_)
            vbuf[cb^1][tid] = *(const float4*)(msrc + row0 + (size_t)(t+1) * D_);

        const float* base = (const float*)vbuf[cb];
        const float* at_ = base;
        const float* w_  = base + 64;
        const float* bt_ = base + 128;
        const float* k_  = base + 192;
        const float* r_  = base + 256;
        const float* vv  = base + 320;

        float atr[8], wr[8], btr[8], kr[8], rr[8];
        LOAD8(atr, at_ + kb); LOAD8(wr, w_ + kb); LOAD8(btr, bt_ + kb);
        LOAD8(kr,  k_  + kb); LOAD8(rr, r_ + kb);
        float vt = vv[vl];

        float p = 0.f;
        #pragma unroll
        for (int i = 0; i < 8; i++) p += s[i] * atr[i];
        redA[kg][vl] = p;
        __syncthreads();

        float sa = 0.f;
        #pragma unroll
        for (int g2 = 0; g2 < 8; g2++) sa += redA[g2][vl];

        float y = 0.f;
        #pragma unroll
        for (int i = 0; i < 8; i++) {
            float sn = s[i]*wr[i] + sa*btr[i] + vt*kr[i];
            s[i] = sn;
            y += sn * rr[i];
        }
        redY[kg][vl] = y;
        __syncthreads();

        if (kg == 0) {
            float yy = 0.f;
            #pragma unroll
            for (int g2 = 0; g2 < 8; g2++) yy += redY[g2][vl];
            Y[row0 + (size_t)t*D_ + h*HS_ + half*32 + vl] = yy;
        }
    }
    // final state: S[((b*H+h)*64 + v)*64 + k]
    int v = half*32 + vl;
    size_t sb = ((size_t)(b*H_ + h)*HS_ + v)*HS_ + kb;
    *(float4*)(S + sb)     = make_float4(s[0], s[1], s[2], s[3]);
    *(float4*)(S + sb + 4) = make_float4(s[4], s[5], s[6], s[7]);
}

// ---------------- per-head groupnorm + residual + gate --------------------------
__launch_bounds__(512)
__global__ void gn_kernel(const float* __restrict__ Y, const float* __restrict__ V_,
    const float* __restrict__ G_, const float* __restrict__ RKS,
    const float* __restrict__ gsc, const float* __restrict__ gbi,
    float* __restrict__ Z)
{
    int bt = blockIdx.x;
    int h = threadIdx.x >> 5, lane = threadIdx.x & 31;
    int base = bt * D_ + h * HS_;
    int i0 = base + lane, i1 = i0 + 32;
    int ce0 = h*HS_ + lane, ce1 = ce0 + 32;
    float y0 = Y[i0], y1 = Y[i1];
    float sm = y0 + y1, sq = y0*y0 + y1*y1;
    #pragma unroll
    for (int o = 16; o; o >>= 1) {
        sm += __shfl_xor_sync(0xffffffffu, sm, o);
        sq += __shfl_xor_sync(0xffffffffu, sq, o);
    }
    float mu  = sm * (1.f/64.f);
    float var = sq * (1.f/64.f) - mu*mu;
    float inv = rsqrtf(var + 1e-5f);
    float rk  = RKS[bt*H_ + h];
    float o0 = (y0 - mu)*inv*gsc[ce0] + gbi[ce0] + rk*V_[i0];
    float o1 = (y1 - mu)*inv*gsc[ce1] + gbi[ce1] + rk*V_[i1];
    Z[i0] = o0 * G_[i0];
    Z[i1] = o1 * G_[i1];
}

// ---------------- launch ---------------------------------------------------------
extern "C" void kernel_launch(void* const* d_in, const int* in_sizes, int n_in,
                              void* d_out, int out_size)
{
    const float* cur    = (const float*)d_in[0];
    const float* prev   = (const float*)d_in[1];
    const float* vfirst = (const float*)d_in[2];
    const float* lam    = (const float*)d_in[3];   // rwkvag (6,D)
    const float* rw_W   = (const float*)d_in[4];
    const float* w1     = (const float*)d_in[5];
    const float* w2     = (const float*)d_in[6];
    const float* w2b    = (const float*)d_in[7];
    const float* kw     = (const float*)d_in[8];
    const float* vw     = (const float*)d_in[9];
    const float* a1     = (const float*)d_in[10];
    const float* a2     = (const float*)d_in[11];
    const float* a2b    = (const float*)d_in[12];
    const float* v1     = (const float*)d_in[13];
    const float* v2     = (const float*)d_in[14];
    const float* v2b    = (const float*)d_in[15];
    const float* g1     = (const float*)d_in[16];
    const float* g2     = (const float*)d_in[17];
    const float* g2b    = (const float*)d_in[18];
    const float* k_k    = (const float*)d_in[19];
    const float* k_a    = (const float*)d_in[20];
    const float* r_k    = (const float*)d_in[21];
    const float* gsc    = (const float*)d_in[22];
    const float* gbi    = (const float*)d_in[23];
    const float* outW   = (const float*)d_in[24];
    (void)in_sizes; (void)n_in;

    float *pr,*pwl,*pk,*pv,*pa,*pg,*pat,*pbt,*phv,*phw,*pha,*phv1,*phg,*prks,*py,*pz,*pds;
    cudaGetSymbolAddress((void**)&pr,  g_r);
    cudaGetSymbolAddress((void**)&pwl, g_wl);
    cudaGetSymbolAddress((void**)&pk,  g_k);
    cudaGetSymbolAddress((void**)&pv,  g_v);
    cudaGetSymbolAddress((void**)&pa,  g_a);
    cudaGetSymbolAddress((void**)&pg,  g_g);
    cudaGetSymbolAddress((void**)&pat, g_at);
    cudaGetSymbolAddress((void**)&pbt, g_bt);
    cudaGetSymbolAddress((void**)&phv, g_hv);
    cudaGetSymbolAddress((void**)&phw, g_hw);
    cudaGetSymbolAddress((void**)&pha, g_ha);
    cudaGetSymbolAddress((void**)&phv1,g_hv1);
    cudaGetSymbolAddress((void**)&phg, g_hg);
    cudaGetSymbolAddress((void**)&prks,g_rks);
    cudaGetSymbolAddress((void**)&py,  g_y);
    cudaGetSymbolAddress((void**)&pz,  g_z);
    cudaGetSymbolAddress((void**)&pds, g_ds);

    float* out = (float*)d_out;
    const int YN = BT_*D_;
    const int SN = B_*H_*HS_*HS_;
    float* stateOut = (out_size >= YN + SN) ? (out + YN) : pds;

    dim3 tb(256);
    // big projections with fused token-shift mix (rows of rwkvag: 0=r 1=w 2=k 3=v 4=a 5=g)
    sgemm<128,128,8,8,8,1,0,0><<<dim3(8,32),tb>>>(nullptr,cur,prev,lam+0*D_,rw_W,nullptr,pr, BT_,D_, D_);
    sgemm<128,128,8,8,8,1,0,0><<<dim3(8,32),tb>>>(nullptr,cur,prev,lam+2*D_,kw,  nullptr,pk, BT_,D_, D_);
    sgemm<128,128,8,8,8,1,0,0><<<dim3(8,32),tb>>>(nullptr,cur,prev,lam+3*D_,vw,  nullptr,pv, BT_,D_, D_);
    // LoRA stage 1
    sgemm<128, 64,8,8,4,1,1,0><<<dim3(1,32),tb>>>(nullptr,cur,prev,lam+1*D_,w1,nullptr,phw, BT_, 64,D_);  // tanh
    sgemm<128, 64,8,8,4,1,0,0><<<dim3(1,32),tb>>>(nullptr,cur,prev,lam+4*D_,a1,nullptr,pha, BT_, 64,D_);
    sgemm<128, 32,8,8,2,1,0,0><<<dim3(1,32),tb>>>(nullptr,cur,prev,lam+3*D_,v1,nullptr,phv1,BT_, 32,D_);
    sgemm<128,128,8,8,8,1,2,0><<<dim3(1,32),tb>>>(nullptr,cur,prev,lam+5*D_,g1,nullptr,phg, BT_,128,D_);  // sigmoid
    // LoRA stage 2
    sgemm<128,128,8,8,8,0,0,1><<<dim3(8,32),tb>>>(phw, nullptr,nullptr,nullptr,w2,w2b,pwl,BT_,D_, 64);
    sgemm<128,128,8,8,8,0,2,1><<<dim3(8,32),tb>>>(pha, nullptr,nullptr,nullptr,a2,a2b,pa, BT_,D_, 64);   // sigmoid
    sgemm<128,128,8,8,8,0,2,1><<<dim3(8,32),tb>>>(phv1,nullptr,nullptr,nullptr,v2,v2b,phv,BT_,D_, 32);   // sigmoid
    sgemm<128,128,8,8,8,0,0,1><<<dim3(8,32),tb>>>(phg, nullptr,nullptr,nullptr,g2,g2b,pg, BT_,D_,128);

    post_kernel<<<BT_,512>>>(pk,pv,pwl,pa,pr,phv,vfirst,k_k,k_a,r_k,pat,pbt,prks);
    scan_kernel<<<128,256>>>(pr,pwl,pk,pv,pat,pbt,py,stateOut);
    gn_kernel<<<BT_,512>>>(py,pv,pg,prks,gsc,gbi,pz);

    // output projection straight into d_out
    sgemm<128,128,8,8,8,0,0,0><<<dim3(8,32),tb>>>(pz,nullptr,nullptr,nullptr,outW,nullptr,out,BT_,D_,D_);

    if (out_size >= YN + SN + YN)
        cudaMemcpyAsync(out + YN + SN, vfirst, (size_t)YN*sizeof(float),
                        cudaMemcpyDeviceToDevice, 0);
}

// round 2
// speedup vs baseline: 1.4025x; 1.4025x over previous
#include <cuda_runtime.h>
#include <math.h>

#define B_ 4
#define T_ 1024
#define D_ 1024
#define H_ 16
#define HS_ 64
#define BT_ (B_*T_)
#define DECAY_C (-0.606531f)

// ---------------- scratch (device globals; no allocation allowed) ----------------
__device__ float g_r  [BT_*D_];
__device__ float g_wl [BT_*D_];
__device__ float g_k  [BT_*D_];
__device__ float g_v  [BT_*D_];
__device__ float g_a  [BT_*D_];
__device__ float g_g  [BT_*D_];
__device__ float g_at [BT_*D_];
__device__ float g_bt [BT_*D_];
__device__ float g_hv [BT_*D_];
__device__ float g_hw [BT_*64];
__device__ float g_ha [BT_*64];
__device__ float g_hv1[BT_*32];
__device__ float g_hg [BT_*128];
__device__ float g_rks[BT_*H_];
__device__ float g_y  [BT_*D_];
__device__ float g_z  [BT_*D_];
__device__ float g_ds [B_*H_*HS_*HS_];

// =====================================================================
// fp32 GEMM core: BM=BN=128, BK=16, TM=TN=8, 256 threads, double-buffered
// MIX fuses token-shift: A[m][k] = cur + lam[k]*(prev-cur)
// =====================================================================
template<int MIX>
__device__ __forceinline__ void gemm128_core(
    const float* __restrict__ A, const float* __restrict__ cur,
    const float* __restrict__ prev, const float* __restrict__ lam,
    const float* __restrict__ Bm, const float* __restrict__ bias,
    float* __restrict__ C, int N, int K, int act,
    float* sA, float* sB)
{
    const int tid  = threadIdx.x;
    const int brow = blockIdx.y * 128;
    const int bcol = blockIdx.x * 128;
    const int arow = tid >> 2;          // 0..63
    const int akq  = (tid & 3) << 2;    // 0,4,8,12
    const int brl  = tid >> 5;          // 0..7
    const int bcl  = (tid & 31) << 2;   // 0..124
    const int trow = (tid >> 4) << 3;
    const int tcol = (tid & 15) << 3;

    float acc[8][8];
    #pragma unroll
    for (int i = 0; i < 8; i++)
        #pragma unroll
        for (int j = 0; j < 8; j++) acc[i][j] = 0.f;

    float4 aG0, aG1, bG0, bG1;

    auto LDA = [&](int k0, int rofs) -> float4 {
        const int g = (brow + arow + rofs) * K + k0 + akq;
        if (MIX) {
            float4 c = *(const float4*)(cur + g);
            float4 p = *(const float4*)(prev + g);
            float4 l = *(const float4*)(lam + k0 + akq);
            return make_float4(fmaf(l.x, p.x - c.x, c.x),
                               fmaf(l.y, p.y - c.y, c.y),
                               fmaf(l.z, p.z - c.z, c.z),
                               fmaf(l.w, p.w - c.w, c.w));
        } else {
            return *(const float4*)(A + g);
        }
    };

    auto LDG_TILE = [&](int k0) {
        aG0 = LDA(k0, 0);
        aG1 = LDA(k0, 64);
        bG0 = *(const float4*)(Bm + (k0 + brl)     * N + bcol + bcl);
        bG1 = *(const float4*)(Bm + (k0 + brl + 8) * N + bcol + bcl);
    };

    auto ST_TILE = [&](int buf) {
        float* Ab = sA + buf * 2112;   // 16*132
        Ab[(akq+0)*132 + arow] = aG0.x;
        Ab[(akq+1)*132 + arow] = aG0.y;
        Ab[(akq+2)*132 + arow] = aG0.z;
        Ab[(akq+3)*132 + arow] = aG0.w;
        Ab[(akq+0)*132 + arow + 64] = aG1.x;
        Ab[(akq+1)*132 + arow + 64] = aG1.y;
        Ab[(akq+2)*132 + arow + 64] = aG1.z;
        Ab[(akq+3)*132 + arow + 64] = aG1.w;
        float* Bb = sB + buf * 2048;   // 16*128
        *(float4*)(Bb + brl * 128 + bcl)       = bG0;
        *(float4*)(Bb + (brl + 8) * 128 + bcl) = bG1;
    };

    LDG_TILE(0);
    ST_TILE(0);
    __syncthreads();

    const int nT = K >> 4;
    for (int t = 0; t < nT; t++) {
        const int buf = t & 1;
        if (t + 1 < nT) LDG_TILE((t + 1) << 4);

        const float* Ab = sA + buf * 2112;
        const float* Bb = sB + buf * 2048;
        #pragma unroll
        for (int kk = 0; kk < 16; kk++) {
            float4 x0 = *(const float4*)(Ab + kk*132 + trow);
            float4 x1 = *(const float4*)(Ab + kk*132 + trow + 4);
            float4 y0 = *(const float4*)(Bb + kk*128 + tcol);
            float4 y1 = *(const float4*)(Bb + kk*128 + tcol + 4);
            float av[8] = {x0.x,x0.y,x0.z,x0.w,x1.x,x1.y,x1.z,x1.w};
            float bv[8] = {y0.x,y0.y,y0.z,y0.w,y1.x,y1.y,y1.z,y1.w};
            #pragma unroll
            for (int i = 0; i < 8; i++)
                #pragma unroll
                for (int j = 0; j < 8; j++)
                    acc[i][j] = fmaf(av[i], bv[j], acc[i][j]);
        }
        if (t + 1 < nT) ST_TILE(buf ^ 1);
        __syncthreads();
    }

    #pragma unroll
    for (int i = 0; i < 8; i++) {
        #pragma unroll
        for (int j = 0; j < 8; j++) {
            float v = acc[i][j];
            if (bias) v += bias[bcol + tcol + j];
            if (act == 1) v = tanhf(v);
            else if (act == 2) v = 1.f / (1.f + expf(-v));
            acc[i][j] = v;
        }
        float* cp = C + (size_t)(brow + trow + i) * N + bcol + tcol;
        *(float4*)(cp)     = make_float4(acc[i][0], acc[i][1], acc[i][2], acc[i][3]);
        *(float4*)(cp + 4) = make_float4(acc[i][4], acc[i][5], acc[i][6], acc[i][7]);
    }
}

// r/k/v projections fused over gridDim.z (mix rows 0,2,3)
__global__ __launch_bounds__(256,2) void rkv_kernel(
    const float* __restrict__ cur, const float* __restrict__ prev,
    const float* __restrict__ lam,
    const float* __restrict__ rw, const float* __restrict__ kw, const float* __restrict__ vw,
    float* __restrict__ pr, float* __restrict__ pk, float* __restrict__ pv)
{
    __shared__ float sA[2*16*132];
    __shared__ float sB[2*16*128];
    int z = blockIdx.z;
    const float* W  = (z == 0) ? rw : (z == 1) ? kw : vw;
    const float* lr = lam + ((z == 0) ? 0 : (z == 1) ? 2 : 3) * D_;
    float* Cc       = (z == 0) ? pr : (z == 1) ? pk : pv;
    gemm128_core<1>(nullptr, cur, prev, lr, W, nullptr, Cc, D_, D_, 0, sA, sB);
}

// LoRA stage-2 fused over z (K=64/64/32/128)
__global__ __launch_bounds__(256,2) void stage2_kernel(
    const float* __restrict__ phw, const float* __restrict__ pha,
    const float* __restrict__ phv1, const float* __restrict__ phg,
    const float* __restrict__ w2, const float* __restrict__ a2,
    const float* __restrict__ v2, const float* __restrict__ g2,
    const float* __restrict__ w2b, const float* __restrict__ a2b,
    const float* __restrict__ v2b, const float* __restrict__ g2b,
    float* __restrict__ pwl, float* __restrict__ pa,
    float* __restrict__ phv, float* __restrict__ pg)
{
    __shared__ float sA[2*16*132];
    __shared__ float sB[2*16*128];
    int z = blockIdx.z;
    const float* A; const float* Bm; const float* bias; float* Cc; int K; int act;
    switch (z) {
        case 0:  A = phw;  Bm = w2; bias = w2b; Cc = pwl; K = 64;  act = 0; break;
        case 1:  A = pha;  Bm = a2; bias = a2b; Cc = pa;  K = 64;  act = 2; break;
        case 2:  A = phv1; Bm = v2; bias = v2b; Cc = phv; K = 32;  act = 2; break;
        default: A = phg;  Bm = g2; bias = g2b; Cc = pg;  K = 128; act = 0; break;
    }
    gemm128_core<0>(A, nullptr, nullptr, nullptr, Bm, bias, Cc, D_, K, act, sA, sB);
}

// output projection
__global__ __launch_bounds__(256,2) void out_kernel(
    const float* __restrict__ pz, const float* __restrict__ W, float* __restrict__ out)
{
    __shared__ float sA[2*16*132];
    __shared__ float sB[2*16*128];
    gemm128_core<0>(pz, nullptr, nullptr, nullptr, W, nullptr, out, D_, D_, 0, sA, sB);
}

// =====================================================================
// LoRA stage-1: all 4 branches in ONE launch. 9 column-tiles of 32:
// tiles 0-1: w1(tanh), 2-3: a1, 4: v1, 5-8: g1(sigmoid). grid=(9,32),128 thr.
// =====================================================================
__global__ __launch_bounds__(128) void lora1_kernel(
    const float* __restrict__ cur, const float* __restrict__ prev,
    const float* __restrict__ lam,
    const float* __restrict__ w1, const float* __restrict__ a1,
    const float* __restrict__ v1, const float* __restrict__ g1,
    float* __restrict__ phw, float* __restrict__ pha,
    float* __restrict__ phv1, float* __restrict__ phg)
{
    __shared__ float sA[2*16*132];
    __shared__ float sB[2*16*32];

    const int tile = blockIdx.x;
    const float* Bm; float* Cout; const float* lr; int act; int ldb; int cofs;
    if (tile < 2)      { Bm = w1; ldb = 64;  cofs = tile * 32;      Cout = phw;  act = 1; lr = lam + 1*D_; }
    else if (tile < 4) { Bm = a1; ldb = 64;  cofs = (tile-2) * 32;  Cout = pha;  act = 0; lr = lam + 4*D_; }
    else if (tile == 4){ Bm = v1; ldb = 32;  cofs = 0;              Cout = phv1; act = 0; lr = lam + 3*D_; }
    else               { Bm = g1; ldb = 128; cofs = (tile-5) * 32;  Cout = phg;  act = 2; lr = lam + 5*D_; }

    const int tid  = threadIdx.x;
    const int brow = blockIdx.y * 128;
    const int arow = tid >> 2;           // 0..31
    const int akq  = (tid & 3) << 2;
    const int brl  = tid >> 3;           // 0..15
    const int bcl  = (tid & 7) << 2;     // 0..28
    const int trow = (tid >> 3) << 3;    // 0..120
    const int tcol = (tid & 7) << 2;     // 0..28

    float acc[8][4];
    #pragma unroll
    for (int i = 0; i < 8; i++)
        #pragma unroll
        for (int j = 0; j < 4; j++) acc[i][j] = 0.f;

    float4 aG[4]; float4 bG;

    auto LDG_TILE = [&](int k0) {
        #pragma unroll
        for (int r = 0; r < 4; r++) {
            int g = (brow + arow + r*32) * D_ + k0 + akq;
            float4 c = *(const float4*)(cur + g);
            float4 p = *(const float4*)(prev + g);
            float4 l = *(const float4*)(lr + k0 + akq);
            aG[r] = make_float4(fmaf(l.x, p.x - c.x, c.x),
                                fmaf(l.y, p.y - c.y, c.y),
                                fmaf(l.z, p.z - c.z, c.z),
                                fmaf(l.w, p.w - c.w, c.w));
        }
        bG = *(const float4*)(Bm + (k0 + brl) * ldb + cofs + bcl);
    };
    auto ST_TILE = [&](int buf) {
        float* Ab = sA + buf * 2112;
        #pragma unroll
        for (int r = 0; r < 4; r++) {
            Ab[(akq+0)*132 + arow + r*32] = aG[r].x;
            Ab[(akq+1)*132 + arow + r*32] = aG[r].y;
            Ab[(akq+2)*132 + arow + r*32] = aG[r].z;
            Ab[(akq+3)*132 + arow + r*32] = aG[r].w;
        }
        *(float4*)(sB + buf * 512 + brl * 32 + bcl) = bG;
    };

    LDG_TILE(0);
    ST_TILE(0);
    __syncthreads();

    const int nT = D_ >> 4;
    for (int t = 0; t < nT; t++) {
        const int buf = t & 1;
        if (t + 1 < nT) LDG_TILE((t + 1) << 4);
        const float* Ab = sA + buf * 2112;
        const float* Bb = sB + buf * 512;
        #pragma unroll
        for (int kk = 0; kk < 16; kk++) {
            float4 x0 = *(const float4*)(Ab + kk*132 + trow);
            float4 x1 = *(const float4*)(Ab + kk*132 + trow + 4);
            float4 y0 = *(const float4*)(Bb + kk*32 + tcol);
            float av[8] = {x0.x,x0.y,x0.z,x0.w,x1.x,x1.y,x1.z,x1.w};
            float bv[4] = {y0.x,y0.y,y0.z,y0.w};
            #pragma unroll
            for (int i = 0; i < 8; i++)
                #pragma unroll
                for (int j = 0; j < 4; j++)
                    acc[i][j] = fmaf(av[i], bv[j], acc[i][j]);
        }
        if (t + 1 < nT) ST_TILE(buf ^ 1);
        __syncthreads();
    }

    #pragma unroll
    for (int i = 0; i < 8; i++) {
        #pragma unroll
        for (int j = 0; j < 4; j++) {
            float v = acc[i][j];
            if (act == 1) v = tanhf(v);
            else if (act == 2) v = 1.f / (1.f + expf(-v));
            acc[i][j] = v;
        }
        float* cp = Cout + (size_t)(brow + trow + i) * ldb + cofs + tcol;
        *(float4*)cp = make_float4(acc[i][0], acc[i][1], acc[i][2], acc[i][3]);
    }
}

// ---------------- post: kk-norm, k/v modification, decay, rk_sum, at/bt --------
__launch_bounds__(512)
__global__ void post_kernel(float* __restrict__ K_, float* __restrict__ V_,
    float* __restrict__ WL, const float* __restrict__ A_, const float* __restrict__ R_,
    const float* __restrict__ HV, const float* __restrict__ vfirst,
    const float* __restrict__ kkv, const float* __restrict__ kav, const float* __restrict__ rkv,
    float* __restrict__ AT, float* __restrict__ BTt, float* __restrict__ RKS)
{
    int bt = blockIdx.x;
    int h = threadIdx.x >> 5, lane = threadIdx.x & 31;
    int base = bt * D_ + h * HS_;
    int ce0 = h*HS_ + lane, ce1 = ce0 + 32;
    int i0 = base + lane, i1 = i0 + 32;

    float k0 = K_[i0], k1 = K_[i1];
    float kk0 = k0 * kkv[ce0], kk1 = k1 * kkv[ce1];
    float n2 = kk0*kk0 + kk1*kk1;
    #pragma unroll
    for (int o = 16; o; o >>= 1) n2 += __shfl_xor_sync(0xffffffffu, n2, o);
    float inv = rsqrtf(n2);
    kk0 *= inv; kk1 *= inv;

    float a0 = A_[i0], a1 = A_[i1];
    AT[i0] = -kk0;      AT[i1] = -kk1;
    BTt[i0] = kk0 * a0; BTt[i1] = kk1 * a1;

    k0 *= 1.f + (a0 - 1.f) * kav[ce0];
    k1 *= 1.f + (a1 - 1.f) * kav[ce1];
    K_[i0] = k0; K_[i1] = k1;

    float v0 = V_[i0], v1 = V_[i1];
    float hg0 = HV[i0], hg1 = HV[i1];
    v0 += (vfirst[i0] - v0) * hg0;
    v1 += (vfirst[i1] - v1) * hg1;
    V_[i0] = v0; V_[i1] = v1;

    float w0 = WL[i0], w1 = WL[i1];
    WL[i0] = expf(DECAY_C / (1.f + expf(-w0)));
    WL[i1] = expf(DECAY_C / (1.f + expf(-w1)));

    float rs = R_[i0]*k0*rkv[ce0] + R_[i1]*k1*rkv[ce1];
    #pragma unroll
    for (int o = 16; o; o >>= 1) rs += __shfl_xor_sync(0xffffffffu, rs, o);
    if (lane == 0) RKS[bt*H_ + h] = rs;
}

// ---------------- sequential scan over T ---------------------------------------
#define LOAD8(dst, ptr) do { \
    float4 u0 = *(const float4*)(ptr); float4 u1 = *(const float4*)((ptr)+4); \
    dst[0]=u0.x; dst[1]=u0.y; dst[2]=u0.z; dst[3]=u0.w; \
    dst[4]=u1.x; dst[5]=u1.y; dst[6]=u1.z; dst[7]=u1.w; } while(0)

__launch_bounds__(256)
__global__ void scan_kernel(const float* __restrict__ R_, const float* __restrict__ W_,
    const float* __restrict__ K_, const float* __restrict__ V_,
    const float* __restrict__ AT, const float* __restrict__ BTt,
    float* __restrict__ Y, float* __restrict__ S)
{
    __shared__ float4 vbuf[2][88];
    __shared__ float redA[8][32];
    __shared__ float redY[8][32];
    int bid = blockIdx.x;
    int b = bid >> 5; int rem = bid & 31; int h = rem >> 1; int half = rem & 1;
    int tid = threadIdx.x;
    int kg = tid >> 5, vl = tid & 31;
    int kb = kg * 8;

    const float* msrc = nullptr;
    if (tid < 88) {
        const float* bp; int inner;
        if (tid < 80) {
            int arr = tid / 16, q = tid % 16;
            bp = (arr==0) ? AT : (arr==1) ? W_ : (arr==2) ? BTt : (arr==3) ? K_ : R_;
            inner = q * 4;
        } else {
            bp = V_; inner = half*32 + (tid - 80) * 4;
        }
        msrc = bp + h*HS_ + inner;
    }

    float s[8];
    #pragma unroll
    for (int i = 0; i < 8; i++) s[i] = 0.f;

    size_t row0 = (size_t)b * T_ * D_;
    if (tid < 88) vbuf[0][tid] = *(const float4*)(msrc + row0);
    __syncthreads();

    for (int t = 0; t < T_; t++) {
        int cb = t & 1;
        if (tid < 88 && t + 1 < T_)
            vbuf[cb^1][tid] = *(const float4*)(msrc + row0 + (size_t)(t+1) * D_);

        const float* base = (const float*)vbuf[cb];
        const float* at_ = base;
        const float* w_  = base + 64;
        const float* bt_ = base + 128;
        const float* k_  = base + 192;
        const float* r_  = base + 256;
        const float* vv  = base + 320;

        float atr[8], wr[8], btr[8], kr[8], rr[8];
        LOAD8(atr, at_ + kb); LOAD8(wr, w_ + kb); LOAD8(btr, bt_ + kb);
        LOAD8(kr,  k_  + kb); LOAD8(rr, r_ + kb);
        float vt = vv[vl];

        float p = 0.f;
        #pragma unroll
        for (int i = 0; i < 8; i++) p += s[i] * atr[i];
        redA[kg][vl] = p;
        __syncthreads();

        float sa = 0.f;
        #pragma unroll
        for (int g2 = 0; g2 < 8; g2++) sa += redA[g2][vl];

        float y = 0.f;
        #pragma unroll
        for (int i = 0; i < 8; i++) {
            float sn = s[i]*wr[i] + sa*btr[i] + vt*kr[i];
            s[i] = sn;
            y += sn * rr[i];
        }
        redY[kg][vl] = y;
        __syncthreads();

        if (kg == 0) {
            float yy = 0.f;
            #pragma unroll
            for (int g2 = 0; g2 < 8; g2++) yy += redY[g2][vl];
            Y[row0 + (size_t)t*D_ + h*HS_ + half*32 + vl] = yy;
        }
    }
    int v = half*32 + vl;
    size_t sb = ((size_t)(b*H_ + h)*HS_ + v)*HS_ + kb;
    *(float4*)(S + sb)     = make_float4(s[0], s[1], s[2], s[3]);
    *(float4*)(S + sb + 4) = make_float4(s[4], s[5], s[6], s[7]);
}

// ---------------- per-head groupnorm + residual + gate --------------------------
__launch_bounds__(512)
__global__ void gn_kernel(const float* __restrict__ Y, const float* __restrict__ V_,
    const float* __restrict__ G_, const float* __restrict__ RKS,
    const float* __restrict__ gsc, const float* __restrict__ gbi,
    float* __restrict__ Z)
{
    int bt = blockIdx.x;
    int h = threadIdx.x >> 5, lane = threadIdx.x & 31;
    int base = bt * D_ + h * HS_;
    int i0 = base + lane, i1 = i0 + 32;
    int ce0 = h*HS_ + lane, ce1 = ce0 + 32;
    float y0 = Y[i0], y1 = Y[i1];
    float sm = y0 + y1, sq = y0*y0 + y1*y1;
    #pragma unroll
    for (int o = 16; o; o >>= 1) {
        sm += __shfl_xor_sync(0xffffffffu, sm, o);
        sq += __shfl_xor_sync(0xffffffffu, sq, o);
    }
    float mu  = sm * (1.f/64.f);
    float var = sq * (1.f/64.f) - mu*mu;
    float inv = rsqrtf(var + 1e-5f);
    float rk  = RKS[bt*H_ + h];
    float o0 = (y0 - mu)*inv*gsc[ce0] + gbi[ce0] + rk*V_[i0];
    float o1 = (y1 - mu)*inv*gsc[ce1] + gbi[ce1] + rk*V_[i1];
    Z[i0] = o0 * G_[i0];
    Z[i1] = o1 * G_[i1];
}

// ---------------- launch ---------------------------------------------------------
extern "C" void kernel_launch(void* const* d_in, const int* in_sizes, int n_in,
                              void* d_out, int out_size)
{
    const float* cur    = (const float*)d_in[0];
    const float* prev   = (const float*)d_in[1];
    const float* vfirst = (const float*)d_in[2];
    const float* lam    = (const float*)d_in[3];
    const float* rw_W   = (const float*)d_in[4];
    const float* w1     = (const float*)d_in[5];
    const float* w2     = (const float*)d_in[6];
    const float* w2b    = (const float*)d_in[7];
    const float* kw     = (const float*)d_in[8];
    const float* vw     = (const float*)d_in[9];
    const float* a1     = (const float*)d_in[10];
    const float* a2     = (const float*)d_in[11];
    const float* a2b    = (const float*)d_in[12];
    const float* v1     = (const float*)d_in[13];
    const float* v2     = (const float*)d_in[14];
    const float* v2b    = (const float*)d_in[15];
    const float* g1     = (const float*)d_in[16];
    const float* g2     = (const float*)d_in[17];
    const float* g2b    = (const float*)d_in[18];
    const float* k_k    = (const float*)d_in[19];
    const float* k_a    = (const float*)d_in[20];
    const float* r_k    = (const float*)d_in[21];
    const float* gsc    = (const float*)d_in[22];
    const float* gbi    = (const float*)d_in[23];
    const float* outW   = (const float*)d_in[24];
    (void)in_sizes; (void)n_in;

    float *pr,*pwl,*pk,*pv,*pa,*pg,*pat,*pbt,*phv,*phw,*pha,*phv1,*phg,*prks,*py,*pz,*pds;
    cudaGetSymbolAddress((void**)&pr,  g_r);
    cudaGetSymbolAddress((void**)&pwl, g_wl);
    cudaGetSymbolAddress((void**)&pk,  g_k);
    cudaGetSymbolAddress((void**)&pv,  g_v);
    cudaGetSymbolAddress((void**)&pa,  g_a);
    cudaGetSymbolAddress((void**)&pg,  g_g);
    cudaGetSymbolAddress((void**)&pat, g_at);
    cudaGetSymbolAddress((void**)&pbt, g_bt);
    cudaGetSymbolAddress((void**)&phv, g_hv);
    cudaGetSymbolAddress((void**)&phw, g_hw);
    cudaGetSymbolAddress((void**)&pha, g_ha);
    cudaGetSymbolAddress((void**)&phv1,g_hv1);
    cudaGetSymbolAddress((void**)&phg, g_hg);
    cudaGetSymbolAddress((void**)&prks,g_rks);
    cudaGetSymbolAddress((void**)&py,  g_y);
    cudaGetSymbolAddress((void**)&pz,  g_z);
    cudaGetSymbolAddress((void**)&pds, g_ds);

    float* out = (float*)d_out;
    const int YN = BT_*D_;
    const int SN = B_*H_*HS_*HS_;
    float* stateOut = (out_size >= YN + SN) ? (out + YN) : pds;

    rkv_kernel   <<<dim3(8,32,3), 256>>>(cur, prev, lam, rw_W, kw, vw, pr, pk, pv);
    lora1_kernel <<<dim3(9,32),   128>>>(cur, prev, lam, w1, a1, v1, g1, phw, pha, phv1, phg);
    stage2_kernel<<<dim3(8,32,4), 256>>>(phw, pha, phv1, phg, w2, a2, v2, g2,
                                         w2b, a2b, v2b, g2b, pwl, pa, phv, pg);
    post_kernel  <<<BT_, 512>>>(pk, pv, pwl, pa, pr, phv, vfirst, k_k, k_a, r_k, pat, pbt, prks);
    scan_kernel  <<<128, 256>>>(pr, pwl, pk, pv, pat, pbt, py, stateOut);
    gn_kernel    <<<BT_, 512>>>(py, pv, pg, prks, gsc, gbi, pz);
    out_kernel   <<<dim3(8,32),  256>>>(pz, outW, out);

    if (out_size >= YN + SN + YN)
        cudaMemcpyAsync(out + YN + SN, vfirst, (size_t)YN*sizeof(float),
                        cudaMemcpyDeviceToDevice, 0);
}

// round 4
// speedup vs baseline: 1.8641x; 1.3291x over previous
#include <cuda_runtime.h>
#include <cuda_bf16.h>
#include <math.h>
#include <stdint.h>

#define B_ 4
#define T_ 1024
#define D_ 1024
#define H_ 16
#define HS_ 64
#define BT_ (B_*T_)
#define DECAY_C (-0.606531f)

// ---------------- scratch ----------------
__device__ float g_r  [BT_*D_];
__device__ float g_wl [BT_*D_];
__device__ float g_k  [BT_*D_];
__device__ float g_v  [BT_*D_];
__device__ float g_a  [BT_*D_];
__device__ float g_g  [BT_*D_];
__device__ float g_at [BT_*D_];
__device__ float g_bt [BT_*D_];
__device__ float g_hv [BT_*D_];
__device__ float g_hw [BT_*64];
__device__ float g_ha [BT_*64];
__device__ float g_hv1[BT_*32];
__device__ float g_hg [BT_*128];
__device__ float g_rks[BT_*H_];
__device__ float g_y  [BT_*D_];
__device__ float g_ds [B_*H_*HS_*HS_];

// bf16 split operands for tensor-core path
__device__ __align__(16) __nv_bfloat16 g_whiT[4][1024*1024];  // W^T hi  (WT[n][k])
__device__ __align__(16) __nv_bfloat16 g_wloT[4][1024*1024];  // W^T lo
__device__ __align__(16) __nv_bfloat16 g_ahi[3][BT_*D_];      // mixed activations hi (r,k,v)
__device__ __align__(16) __nv_bfloat16 g_alo[3][BT_*D_];
__device__ __align__(16) __nv_bfloat16 g_zhi[BT_*D_];
__device__ __align__(16) __nv_bfloat16 g_zlo[BT_*D_];

// ================= low-level helpers =================
__device__ __forceinline__ uint32_t smem_to_u32(const void* p) {
    uint32_t a;
    asm("{ .reg .u64 t; cvta.to.shared.u64 t, %1; cvt.u32.u64 %0, t; }" : "=r"(a) : "l"(p));
    return a;
}
__device__ __forceinline__ void cpasync16(uint32_t saddr, const void* g) {
    asm volatile("cp.async.cg.shared.global [%0], [%1], 16;" :: "r"(saddr), "l"(g));
}
#define CP_COMMIT() asm volatile("cp.async.commit_group;" ::: "memory")
#define CP_WAIT1()  asm volatile("cp.async.wait_group 1;" ::: "memory")
#define CP_WAIT0()  asm volatile("cp.async.wait_group 0;" ::: "memory")

__device__ __forceinline__ void ldsm4(uint32_t* r, uint32_t addr) {
    asm volatile("ldmatrix.sync.aligned.m8n8.x4.shared.b16 {%0,%1,%2,%3}, [%4];"
                 : "=r"(r[0]), "=r"(r[1]), "=r"(r[2]), "=r"(r[3]) : "r"(addr));
}
__device__ __forceinline__ void ldsm2(uint32_t* r, uint32_t addr) {
    asm volatile("ldmatrix.sync.aligned.m8n8.x2.shared.b16 {%0,%1}, [%2];"
                 : "=r"(r[0]), "=r"(r[1]) : "r"(addr));
}
__device__ __forceinline__ void mma16816(float* d, const uint32_t* a, const uint32_t* b) {
    asm volatile("mma.sync.aligned.m16n8k16.row.col.f32.bf16.bf16.f32 "
                 "{%0,%1,%2,%3}, {%4,%5,%6,%7}, {%8,%9}, {%0,%1,%2,%3};"
                 : "+f"(d[0]), "+f"(d[1]), "+f"(d[2]), "+f"(d[3])
                 : "r"(a[0]), "r"(a[1]), "r"(a[2]), "r"(a[3]), "r"(b[0]), "r"(b[1]));
}

__device__ __forceinline__ void split_bf(float x, __nv_bfloat16& h, __nv_bfloat16& l) {
    h = __float2bfloat16(x);
    l = __float2bfloat16(x - __bfloat162float(h));
}

// ================= prep kernels =================
__global__ __launch_bounds__(256) void wsplit_kernel(
    const float* __restrict__ w0, const float* __restrict__ w1,
    const float* __restrict__ w2, const float* __restrict__ w3)
{
    const float* W = (blockIdx.z==0)?w0:(blockIdx.z==1)?w1:(blockIdx.z==2)?w2:w3;
    __nv_bfloat16* HT = g_whiT[blockIdx.z];
    __nv_bfloat16* LT = g_wloT[blockIdx.z];
    __shared__ float ts[32][33];
    int tx = threadIdx.x & 31, ty = threadIdx.x >> 5;
    int k0 = blockIdx.y*32, n0 = blockIdx.x*32;
    #pragma unroll
    for (int i = 0; i < 4; i++)
        ts[ty+i*8][tx] = W[(size_t)(k0+ty+i*8)*1024 + n0+tx];
    __syncthreads();
    #pragma unroll
    for (int i = 0; i < 4; i++) {
        int r = ty + i*8;
        float v = ts[tx][r];
        __nv_bfloat16 h, l; split_bf(v, h, l);
        HT[(size_t)(n0+r)*1024 + k0+tx] = h;
        LT[(size_t)(n0+r)*1024 + k0+tx] = l;
    }
}

__global__ __launch_bounds__(256) void asplit_kernel(
    const float* __restrict__ cur, const float* __restrict__ prev,
    const float* __restrict__ lam)
{
    int z = blockIdx.y;
    const float* lr = lam + ((z==0)?0:(z==1)?2:3)*D_;
    __nv_bfloat16* hi = g_ahi[z];
    __nv_bfloat16* lo = g_alo[z];
    size_t e = ((size_t)blockIdx.x*256 + threadIdx.x)*4;
    float4 c = *(const float4*)(cur+e);
    float4 p = *(const float4*)(prev+e);
    int col = (int)(e & 1023);
    float4 l4 = *(const float4*)(lr+col);
    float m0 = fmaf(l4.x, p.x-c.x, c.x), m1 = fmaf(l4.y, p.y-c.y, c.y);
    float m2 = fmaf(l4.z, p.z-c.z, c.z), m3 = fmaf(l4.w, p.w-c.w, c.w);
    __nv_bfloat16 h0,l0,h1,l1,h2,l2,h3,l3;
    split_bf(m0,h0,l0); split_bf(m1,h1,l1); split_bf(m2,h2,l2); split_bf(m3,h3,l3);
    __nv_bfloat162* hp = (__nv_bfloat162*)(hi+e);
    __nv_bfloat162* lp = (__nv_bfloat162*)(lo+e);
    hp[0] = __nv_bfloat162(h0,h1); hp[1] = __nv_bfloat162(h2,h3);
    lp[0] = __nv_bfloat162(l0,l1); lp[1] = __nv_bfloat162(l2,l3);
}

// ================= HMMA split-bf16 GEMM (mma.sync) =================
// C[4096x1024] = A[4096x1024] * W, with A,W given as bf16 hi/lo and WT (N-major).
// 3-pass compensation: Ahi*Bhi + Ahi*Blo + Alo*Bhi into one f32 accumulator.
struct TCSet { const __nv_bfloat16 *ahi, *alo, *bhi, *blo; float* c; };
struct TCParams { TCSet s[3]; };

#define MMA_STRIDE 40                 // padded smem row stride (bf16 elems)
#define TILE_ELE (128*MMA_STRIDE)     // elems per tile buffer
#define MMA_SMEM_BYTES (2*4*TILE_ELE*2)   // 2 stages * 4 tiles * bytes

__global__ __launch_bounds__(256) void mma_gemm(TCParams P)
{
    extern __shared__ __align__(16) __nv_bfloat16 sm[];
    const uint32_t smb = smem_to_u32(sm);
    TCSet S = P.s[blockIdx.z];
    const int tid = threadIdx.x, lane = tid & 31, w = tid >> 5;
    const int wm = w & 3, wn = w >> 2;          // warp tile: rows wm*32, cols wn*64
    const int brow = blockIdx.y * 128, bcol = blockIdx.x * 128;

    const __nv_bfloat16* gsrc[4] = {
        S.ahi + (size_t)brow*1024, S.alo + (size_t)brow*1024,
        S.bhi + (size_t)bcol*1024, S.blo + (size_t)bcol*1024 };

    auto issue = [&](int c) {
        const int st = c & 1;
        #pragma unroll
        for (int t4 = 0; t4 < 4; t4++) {
            #pragma unroll
            for (int i = 0; i < 2; i++) {
                int u = i*256 + tid;
                int r = u >> 2, q = u & 3;
                cpasync16(smb + 2u*((uint32_t)(st*4 + t4)*TILE_ELE + r*MMA_STRIDE + q*8),
                          gsrc[t4] + (size_t)r*1024 + c*32 + q*8);
            }
        }
    };

    float acc[2][8][4];
    #pragma unroll
    for (int mi = 0; mi < 2; mi++)
        #pragma unroll
        for (int ni = 0; ni < 8; ni++)
            #pragma unroll
            for (int q = 0; q < 4; q++) acc[mi][ni][q] = 0.f;

    // ldmatrix smem addresses (lane-dependent, stage-invariant offsets)
    const int la15 = lane & 15;
    const int akc  = (lane >> 4) << 3;           // 0 or 8
    const int tt   = lane & 15;
    const int bro  = tt & 7;                     // B row within 8
    const int bkc  = (tt >> 3) << 3;             // 0 or 8

    issue(0); CP_COMMIT();

    for (int c = 0; c < 32; c++) {
        if (c + 1 < 32) { issue(c + 1); CP_COMMIT(); CP_WAIT1(); }
        else            { CP_WAIT0(); }
        __syncthreads();

        const uint32_t stb = smb + 2u*(uint32_t)((c & 1)*4)*TILE_ELE;
        #pragma unroll
        for (int ks = 0; ks < 32; ks += 16) {
            uint32_t ah[2][4], al[2][4];
            #pragma unroll
            for (int mi = 0; mi < 2; mi++) {
                const int row = wm*32 + mi*16 + la15;
                const uint32_t ao = 2u*(row*MMA_STRIDE + ks + akc);
                ldsm4(ah[mi], stb + 0*2*TILE_ELE + ao);
                ldsm4(al[mi], stb + 1*2*TILE_ELE + ao);
            }
            #pragma unroll
            for (int ni = 0; ni < 8; ni++) {
                const int nrow = wn*64 + ni*8 + bro;
                const uint32_t bo = 2u*(nrow*MMA_STRIDE + ks + bkc);
                uint32_t bh[2], bl[2];
                ldsm2(bh, stb + 2*2*TILE_ELE + bo);
                ldsm2(bl, stb + 3*2*TILE_ELE + bo);
                #pragma unroll
                for (int mi = 0; mi < 2; mi++) {
                    mma16816(acc[mi][ni], ah[mi], bh);
                    mma16816(acc[mi][ni], ah[mi], bl);
                    mma16816(acc[mi][ni], al[mi], bh);
                }
            }
        }
        __syncthreads();
    }

    // epilogue: fragment c-layout -> global
    const int g2 = lane >> 2, cc = lane & 3;
    #pragma unroll
    for (int mi = 0; mi < 2; mi++) {
        #pragma unroll
        for (int ni = 0; ni < 8; ni++) {
            const int row = brow + wm*32 + mi*16;
            const int col = bcol + wn*64 + ni*8 + 2*cc;
            *(float2*)(S.c + (size_t)(row + g2    )*1024 + col) = make_float2(acc[mi][ni][0], acc[mi][ni][1]);
            *(float2*)(S.c + (size_t)(row + g2 + 8)*1024 + col) = make_float2(acc[mi][ni][2], acc[mi][ni][3]);
        }
    }
}

// ================= fp32 GEMM core (for LoRA) =================
template<int MIX>
__device__ __forceinline__ void gemm128_core(
    const float* __restrict__ A, const float* __restrict__ cur,
    const float* __restrict__ prev, const float* __restrict__ lam,
    const float* __restrict__ Bm, const float* __restrict__ bias,
    float* __restrict__ C, int N, int K, int act,
    float* sA, float* sB)
{
    const int tid  = threadIdx.x;
    const int brow = blockIdx.y * 128;
    const int bcol = blockIdx.x * 128;
    const int arow = tid >> 2;
    const int akq  = (tid & 3) << 2;
    const int brl  = tid >> 5;
    const int bcl  = (tid & 31) << 2;
    const int trow = (tid >> 4) << 3;
    const int tcol = (tid & 15) << 3;

    float acc[8][8];
    #pragma unroll
    for (int i = 0; i < 8; i++)
        #pragma unroll
        for (int j = 0; j < 8; j++) acc[i][j] = 0.f;

    float4 aG0, aG1, bG0, bG1;
    auto LDA = [&](int k0, int rofs) -> float4 {
        const int g = (brow + arow + rofs) * K + k0 + akq;
        if (MIX) {
            float4 c = *(const float4*)(cur + g);
            float4 p = *(const float4*)(prev + g);
            float4 l = *(const float4*)(lam + k0 + akq);
            return make_float4(fmaf(l.x, p.x - c.x, c.x), fmaf(l.y, p.y - c.y, c.y),
                               fmaf(l.z, p.z - c.z, c.z), fmaf(l.w, p.w - c.w, c.w));
        } else return *(const float4*)(A + g);
    };
    auto LDG_TILE = [&](int k0) {
        aG0 = LDA(k0, 0); aG1 = LDA(k0, 64);
        bG0 = *(const float4*)(Bm + (k0 + brl) * N + bcol + bcl);
        bG1 = *(const float4*)(Bm + (k0 + brl + 8) * N + bcol + bcl);
    };
    auto ST_TILE = [&](int buf) {
        float* Ab = sA + buf * 2112;
        Ab[(akq+0)*132 + arow] = aG0.x; Ab[(akq+1)*132 + arow] = aG0.y;
        Ab[(akq+2)*132 + arow] = aG0.z; Ab[(akq+3)*132 + arow] = aG0.w;
        Ab[(akq+0)*132 + arow+64] = aG1.x; Ab[(akq+1)*132 + arow+64] = aG1.y;
        Ab[(akq+2)*132 + arow+64] = aG1.z; Ab[(akq+3)*132 + arow+64] = aG1.w;
        float* Bb = sB + buf * 2048;
        *(float4*)(Bb + brl*128 + bcl) = bG0;
        *(float4*)(Bb + (brl+8)*128 + bcl) = bG1;
    };

    LDG_TILE(0); ST_TILE(0); __syncthreads();
    const int nT = K >> 4;
    for (int t = 0; t < nT; t++) {
        const int buf = t & 1;
        if (t + 1 < nT) LDG_TILE((t + 1) << 4);
        const float* Ab = sA + buf * 2112;
        const float* Bb = sB + buf * 2048;
        #pragma unroll
        for (int kk = 0; kk < 16; kk++) {
            float4 x0 = *(const float4*)(Ab + kk*132 + trow);
            float4 x1 = *(const float4*)(Ab + kk*132 + trow + 4);
            float4 y0 = *(const float4*)(Bb + kk*128 + tcol);
            float4 y1 = *(const float4*)(Bb + kk*128 + tcol + 4);
            float av[8] = {x0.x,x0.y,x0.z,x0.w,x1.x,x1.y,x1.z,x1.w};
            float bv[8] = {y0.x,y0.y,y0.z,y0.w,y1.x,y1.y,y1.z,y1.w};
            #pragma unroll
            for (int i = 0; i < 8; i++)
                #pragma unroll
                for (int j = 0; j < 8; j++)
                    acc[i][j] = fmaf(av[i], bv[j], acc[i][j]);
        }
        if (t + 1 < nT) ST_TILE(buf ^ 1);
        __syncthreads();
    }
    #pragma unroll
    for (int i = 0; i < 8; i++) {
        #pragma unroll
        for (int j = 0; j < 8; j++) {
            float v = acc[i][j];
            if (bias) v += bias[bcol + tcol + j];
            if (act == 1) v = tanhf(v);
            else if (act == 2) v = 1.f / (1.f + expf(-v));
            acc[i][j] = v;
        }
        float* cp = C + (size_t)(brow + trow + i) * N + bcol + tcol;
        *(float4*)(cp)     = make_float4(acc[i][0], acc[i][1], acc[i][2], acc[i][3]);
        *(float4*)(cp + 4) = make_float4(acc[i][4], acc[i][5], acc[i][6], acc[i][7]);
    }
}

__global__ __launch_bounds__(256,2) void stage2_kernel(
    const float* __restrict__ phw, const float* __restrict__ pha,
    const float* __restrict__ phv1, const float* __restrict__ phg,
    const float* __restrict__ w2, const float* __restrict__ a2,
    const float* __restrict__ v2, const float* __restrict__ g2,
    const float* __restrict__ w2b, const float* __restrict__ a2b,
    const float* __restrict__ v2b, const float* __restrict__ g2b,
    float* __restrict__ pwl, float* __restrict__ pa,
    float* __restrict__ phv, float* __restrict__ pg)
{
    __shared__ float sA[2*16*132];
    __shared__ float sB[2*16*128];
    int z = blockIdx.z;
    const float* A; const float* Bm; const float* bias; float* Cc; int K; int act;
    switch (z) {
        case 0:  A = phw;  Bm = w2; bias = w2b; Cc = pwl; K = 64;  act = 0; break;
        case 1:  A = pha;  Bm = a2; bias = a2b; Cc = pa;  K = 64;  act = 2; break;
        case 2:  A = phv1; Bm = v2; bias = v2b; Cc = phv; K = 32;  act = 2; break;
        default: A = phg;  Bm = g2; bias = g2b; Cc = pg;  K = 128; act = 0; break;
    }
    gemm128_core<0>(A, nullptr, nullptr, nullptr, Bm, bias, Cc, D_, K, act, sA, sB);
}

__global__ __launch_bounds__(128) void lora1_kernel(
    const float* __restrict__ cur, const float* __restrict__ prev,
    const float* __restrict__ lam,
    const float* __restrict__ w1, const float* __restrict__ a1,
    const float* __restrict__ v1, const float* __restrict__ g1,
    float* __restrict__ phw, float* __restrict__ pha,
    float* __restrict__ phv1, float* __restrict__ phg)
{
    __shared__ float sA[2*16*132];
    __shared__ float sB[2*16*32];
    const int tile = blockIdx.x;
    const float* Bm; float* Cout; const float* lr; int act; int ldb; int cofs;
    if (tile < 2)      { Bm = w1; ldb = 64;  cofs = tile * 32;     Cout = phw;  act = 1; lr = lam + 1*D_; }
    else if (tile < 4) { Bm = a1; ldb = 64;  cofs = (tile-2) * 32; Cout = pha;  act = 0; lr = lam + 4*D_; }
    else if (tile == 4){ Bm = v1; ldb = 32;  cofs = 0;             Cout = phv1; act = 0; lr = lam + 3*D_; }
    else               { Bm = g1; ldb = 128; cofs = (tile-5) * 32; Cout = phg;  act = 2; lr = lam + 5*D_; }

    const int tid  = threadIdx.x;
    const int brow = blockIdx.y * 128;
    const int arow = tid >> 2;
    const int akq  = (tid & 3) << 2;
    const int brl  = tid >> 3;
    const int bcl  = (tid & 7) << 2;
    const int trow = (tid >> 3) << 3;
    const int tcol = (tid & 7) << 2;

    float acc[8][4];
    #pragma unroll
    for (int i = 0; i < 8; i++)
        #pragma unroll
        for (int j = 0; j < 4; j++) acc[i][j] = 0.f;

    float4 aG[4]; float4 bG;
    auto LDG_TILE = [&](int k0) {
        #pragma unroll
        for (int r = 0; r < 4; r++) {
            int g = (brow + arow + r*32) * D_ + k0 + akq;
            float4 c = *(const float4*)(cur + g);
            float4 p = *(const float4*)(prev + g);
            float4 l = *(const float4*)(lr + k0 + akq);
            aG[r] = make_float4(fmaf(l.x, p.x - c.x, c.x), fmaf(l.y, p.y - c.y, c.y),
                                fmaf(l.z, p.z - c.z, c.z), fmaf(l.w, p.w - c.w, c.w));
        }
        bG = *(const float4*)(Bm + (k0 + brl) * ldb + cofs + bcl);
    };
    auto ST_TILE = [&](int buf) {
        float* Ab = sA + buf * 2112;
        #pragma unroll
        for (int r = 0; r < 4; r++) {
            Ab[(akq+0)*132 + arow + r*32] = aG[r].x;
            Ab[(akq+1)*132 + arow + r*32] = aG[r].y;
            Ab[(akq+2)*132 + arow + r*32] = aG[r].z;
            Ab[(akq+3)*132 + arow + r*32] = aG[r].w;
        }
        *(float4*)(sB + buf * 512 + brl * 32 + bcl) = bG;
    };

    LDG_TILE(0); ST_TILE(0); __syncthreads();
    const int nT = D_ >> 4;
    for (int t = 0; t < nT; t++) {
        const int buf = t & 1;
        if (t + 1 < nT) LDG_TILE((t + 1) << 4);
        const float* Ab = sA + buf * 2112;
        const float* Bb = sB + buf * 512;
        #pragma unroll
        for (int kk = 0; kk < 16; kk++) {
            float4 x0 = *(const float4*)(Ab + kk*132 + trow);
            float4 x1 = *(const float4*)(Ab + kk*132 + trow + 4);
            float4 y0 = *(const float4*)(Bb + kk*32 + tcol);
            float av[8] = {x0.x,x0.y,x0.z,x0.w,x1.x,x1.y,x1.z,x1.w};
            float bv[4] = {y0.x,y0.y,y0.z,y0.w};
            #pragma unroll
            for (int i = 0; i < 8; i++)
                #pragma unroll
                for (int j = 0; j < 4; j++)
                    acc[i][j] = fmaf(av[i], bv[j], acc[i][j]);
        }
        if (t + 1 < nT) ST_TILE(buf ^ 1);
        __syncthreads();
    }
    #pragma unroll
    for (int i = 0; i < 8; i++) {
        #pragma unroll
        for (int j = 0; j < 4; j++) {
            float v = acc[i][j];
            if (act == 1) v = tanhf(v);
            else if (act == 2) v = 1.f / (1.f + expf(-v));
            acc[i][j] = v;
        }
        float* cp = Cout + (size_t)(brow + trow + i) * ldb + cofs + tcol;
        *(float4*)cp = make_float4(acc[i][0], acc[i][1], acc[i][2], acc[i][3]);
    }
}

// ---------------- post ----------------
__launch_bounds__(512)
__global__ void post_kernel(float* __restrict__ K_, float* __restrict__ V_,
    float* __restrict__ WL, const float* __restrict__ A_, const float* __restrict__ R_,
    const float* __restrict__ HV, const float* __restrict__ vfirst,
    const float* __restrict__ kkv, const float* __restrict__ kav, const float* __restrict__ rkv,
    float* __restrict__ AT, float* __restrict__ BTt, float* __restrict__ RKS)
{
    int bt = blockIdx.x;
    int h = threadIdx.x >> 5, lane = threadIdx.x & 31;
    int base = bt * D_ + h * HS_;
    int ce0 = h*HS_ + lane, ce1 = ce0 + 32;
    int i0 = base + lane, i1 = i0 + 32;

    float k0 = K_[i0], k1 = K_[i1];
    float kk0 = k0 * kkv[ce0], kk1 = k1 * kkv[ce1];
    float n2 = kk0*kk0 + kk1*kk1;
    #pragma unroll
    for (int o = 16; o; o >>= 1) n2 += __shfl_xor_sync(0xffffffffu, n2, o);
    float inv = rsqrtf(n2);
    kk0 *= inv; kk1 *= inv;

    float a0 = A_[i0], a1 = A_[i1];
    AT[i0] = -kk0;      AT[i1] = -kk1;
    BTt[i0] = kk0 * a0; BTt[i1] = kk1 * a1;

    k0 *= 1.f + (a0 - 1.f) * kav[ce0];
    k1 *= 1.f + (a1 - 1.f) * kav[ce1];
    K_[i0] = k0; K_[i1] = k1;

    float v0 = V_[i0], v1 = V_[i1];
    float hg0 = HV[i0], hg1 = HV[i1];
    v0 += (vfirst[i0] - v0) * hg0;
    v1 += (vfirst[i1] - v1) * hg1;
    V_[i0] = v0; V_[i1] = v1;

    float w0 = WL[i0], w1 = WL[i1];
    WL[i0] = expf(DECAY_C / (1.f + expf(-w0)));
    WL[i1] = expf(DECAY_C / (1.f + expf(-w1)));

    float rs = R_[i0]*k0*rkv[ce0] + R_[i1]*k1*rkv[ce1];
    #pragma unroll
    for (int o = 16; o; o >>= 1) rs += __shfl_xor_sync(0xffffffffu, rs, o);
    if (lane == 0) RKS[bt*H_ + h] = rs;
}

// ---------------- scan ----------------
#define LOAD8(dst, ptr) do { \
    float4 u0 = *(const float4*)(ptr); float4 u1 = *(const float4*)((ptr)+4); \
    dst[0]=u0.x; dst[1]=u0.y; dst[2]=u0.z; dst[3]=u0.w; \
    dst[4]=u1.x; dst[5]=u1.y; dst[6]=u1.z; dst[7]=u1.w; } while(0)

__launch_bounds__(256)
__global__ void scan_kernel(const float* __restrict__ R_, const float* __restrict__ W_,
    const float* __restrict__ K_, const float* __restrict__ V_,
    const float* __restrict__ AT, const float* __restrict__ BTt,
    float* __restrict__ Y, float* __restrict__ S)
{
    __shared__ float4 vbuf[2][88];
    __shared__ float redA[8][32];
    __shared__ float redY[8][32];
    int bid = blockIdx.x;
    int b = bid >> 5; int rem = bid & 31; int h = rem >> 1; int half = rem & 1;
    int tid = threadIdx.x;
    int kg = tid >> 5, vl = tid & 31;
    int kb = kg * 8;

    const float* msrc = nullptr;
    if (tid < 88) {
        const float* bp; int inner;
        if (tid < 80) {
            int arr = tid / 16, q = tid % 16;
            bp = (arr==0) ? AT : (arr==1) ? W_ : (arr==2) ? BTt : (arr==3) ? K_ : R_;
            inner = q * 4;
        } else {
            bp = V_; inner = half*32 + (tid - 80) * 4;
        }
        msrc = bp + h*HS_ + inner;
    }

    float s[8];
    #pragma unroll
    for (int i = 0; i < 8; i++) s[i] = 0.f;

    size_t row0 = (size_t)b * T_ * D_;
    if (tid < 88) vbuf[0][tid] = *(const float4*)(msrc + row0);
    __syncthreads();

    for (int t = 0; t < T_; t++) {
        int cb = t & 1;
        if (tid < 88 && t + 1 < T_)
            vbuf[cb^1][tid] = *(const float4*)(msrc + row0 + (size_t)(t+1) * D_);

        const float* base = (const float*)vbuf[cb];
        const float* at_ = base;
        const float* w_  = base + 64;
        const float* bt_ = base + 128;
        const float* k_  = base + 192;
        const float* r_  = base + 256;
        const float* vv  = base + 320;

        float atr[8], wr[8], btr[8], kr[8], rr[8];
        LOAD8(atr, at_ + kb); LOAD8(wr, w_ + kb); LOAD8(btr, bt_ + kb);
        LOAD8(kr,  k_  + kb); LOAD8(rr, r_ + kb);
        float vt = vv[vl];

        float p = 0.f;
        #pragma unroll
        for (int i = 0; i < 8; i++) p += s[i] * atr[i];
        redA[kg][vl] = p;
        __syncthreads();

        float sa = 0.f;
        #pragma unroll
        for (int g2 = 0; g2 < 8; g2++) sa += redA[g2][vl];

        float y = 0.f;
        #pragma unroll
        for (int i = 0; i < 8; i++) {
            float sn = s[i]*wr[i] + sa*btr[i] + vt*kr[i];
            s[i] = sn;
            y += sn * rr[i];
        }
        redY[kg][vl] = y;
        __syncthreads();

        if (kg == 0) {
            float yy = 0.f;
            #pragma unroll
            for (int g2 = 0; g2 < 8; g2++) yy += redY[g2][vl];
            Y[row0 + (size_t)t*D_ + h*HS_ + half*32 + vl] = yy;
        }
    }
    int v = half*32 + vl;
    size_t sb2 = ((size_t)(b*H_ + h)*HS_ + v)*HS_ + kb;
    *(float4*)(S + sb2)     = make_float4(s[0], s[1], s[2], s[3]);
    *(float4*)(S + sb2 + 4) = make_float4(s[4], s[5], s[6], s[7]);
}

// ---------------- groupnorm + residual + gate + bf16 split ----------------
__launch_bounds__(512)
__global__ void gn_kernel(const float* __restrict__ Y, const float* __restrict__ V_,
    const float* __restrict__ G_, const float* __restrict__ RKS,
    const float* __restrict__ gsc, const float* __restrict__ gbi)
{
    int bt = blockIdx.x;
    int h = threadIdx.x >> 5, lane = threadIdx.x & 31;
    int base = bt * D_ + h * HS_;
    int i0 = base + lane, i1 = i0 + 32;
    int ce0 = h*HS_ + lane, ce1 = ce0 + 32;
    float y0 = Y[i0], y1 = Y[i1];
    float sm = y0 + y1, sq = y0*y0 + y1*y1;
    #pragma unroll
    for (int o = 16; o; o >>= 1) {
        sm += __shfl_xor_sync(0xffffffffu, sm, o);
        sq += __shfl_xor_sync(0xffffffffu, sq, o);
    }
    float mu  = sm * (1.f/64.f);
    float var = sq * (1.f/64.f) - mu*mu;
    float inv = rsqrtf(var + 1e-5f);
    float rk  = RKS[bt*H_ + h];
    float o0 = ((y0 - mu)*inv*gsc[ce0] + gbi[ce0] + rk*V_[i0]) * G_[i0];
    float o1 = ((y1 - mu)*inv*gsc[ce1] + gbi[ce1] + rk*V_[i1]) * G_[i1];
    __nv_bfloat16 h0,l0,h1,l1;
    split_bf(o0, h0, l0); split_bf(o1, h1, l1);
    g_zhi[i0] = h0; g_zhi[i1] = h1;
    g_zlo[i0] = l0; g_zlo[i1] = l1;
}

// ---------------- launch ----------------
extern "C" void kernel_launch(void* const* d_in, const int* in_sizes, int n_in,
                              void* d_out, int out_size)
{
    const float* cur    = (const float*)d_in[0];
    const float* prev   = (const float*)d_in[1];
    const float* vfirst = (const float*)d_in[2];
    const float* lam    = (const float*)d_in[3];
    const float* rw_W   = (const float*)d_in[4];
    const float* w1     = (const float*)d_in[5];
    const float* w2     = (const float*)d_in[6];
    const float* w2b    = (const float*)d_in[7];
    const float* kw     = (const float*)d_in[8];
    const float* vw     = (const float*)d_in[9];
    const float* a1     = (const float*)d_in[10];
    const float* a2     = (const float*)d_in[11];
    const float* a2b    = (const float*)d_in[12];
    const float* v1     = (const float*)d_in[13];
    const float* v2     = (const float*)d_in[14];
    const float* v2b    = (const float*)d_in[15];
    const float* g1     = (const float*)d_in[16];
    const float* g2     = (const float*)d_in[17];
    const float* g2b    = (const float*)d_in[18];
    const float* k_k    = (const float*)d_in[19];
    const float* k_a    = (const float*)d_in[20];
    const float* r_k    = (const float*)d_in[21];
    const float* gsc    = (const float*)d_in[22];
    const float* gbi    = (const float*)d_in[23];
    const float* outW   = (const float*)d_in[24];
    (void)in_sizes; (void)n_in;

    float *pr,*pwl,*pk,*pv,*pa,*pg,*pat,*pbt,*phv,*phw,*pha,*phv1,*phg,*prks,*py,*pds;
    cudaGetSymbolAddress((void**)&pr,  g_r);
    cudaGetSymbolAddress((void**)&pwl, g_wl);
    cudaGetSymbolAddress((void**)&pk,  g_k);
    cudaGetSymbolAddress((void**)&pv,  g_v);
    cudaGetSymbolAddress((void**)&pa,  g_a);
    cudaGetSymbolAddress((void**)&pg,  g_g);
    cudaGetSymbolAddress((void**)&pat, g_at);
    cudaGetSymbolAddress((void**)&pbt, g_bt);
    cudaGetSymbolAddress((void**)&phv, g_hv);
    cudaGetSymbolAddress((void**)&phw, g_hw);
    cudaGetSymbolAddress((void**)&pha, g_ha);
    cudaGetSymbolAddress((void**)&phv1,g_hv1);
    cudaGetSymbolAddress((void**)&phg, g_hg);
    cudaGetSymbolAddress((void**)&prks,g_rks);
    cudaGetSymbolAddress((void**)&py,  g_y);
    cudaGetSymbolAddress((void**)&pds, g_ds);

    __nv_bfloat16 *pwhiT, *pwloT, *pahi, *palo, *pzhi, *pzlo;
    cudaGetSymbolAddress((void**)&pwhiT, g_whiT);
    cudaGetSymbolAddress((void**)&pwloT, g_wloT);
    cudaGetSymbolAddress((void**)&pahi,  g_ahi);
    cudaGetSymbolAddress((void**)&palo,  g_alo);
    cudaGetSymbolAddress((void**)&pzhi,  g_zhi);
    cudaGetSymbolAddress((void**)&pzlo,  g_zlo);

    float* out = (float*)d_out;
    const int YN = BT_*D_;
    const int SN = B_*H_*HS_*HS_;
    float* stateOut = (out_size >= YN + SN) ? (out + YN) : pds;

    cudaFuncSetAttribute(mma_gemm, cudaFuncAttributeMaxDynamicSharedMemorySize, MMA_SMEM_BYTES);

    wsplit_kernel<<<dim3(32,32,4), 256>>>(rw_W, kw, vw, outW);
    asplit_kernel<<<dim3(4096,3),  256>>>(cur, prev, lam);

    TCParams Prkv;
    for (int z = 0; z < 3; z++) {
        Prkv.s[z].ahi = pahi + (size_t)z*BT_*D_;
        Prkv.s[z].alo = palo + (size_t)z*BT_*D_;
        Prkv.s[z].bhi = pwhiT + (size_t)z*1024*1024;
        Prkv.s[z].blo = pwloT + (size_t)z*1024*1024;
        Prkv.s[z].c   = (z==0) ? pr : (z==1) ? pk : pv;
    }
    mma_gemm<<<dim3(8,32,3), 256, MMA_SMEM_BYTES>>>(Prkv);

    lora1_kernel <<<dim3(9,32),   128>>>(cur, prev, lam, w1, a1, v1, g1, phw, pha, phv1, phg);
    stage2_kernel<<<dim3(8,32,4), 256>>>(phw, pha, phv1, phg, w2, a2, v2, g2,
                                         w2b, a2b, v2b, g2b, pwl, pa, phv, pg);
    post_kernel  <<<BT_, 512>>>(pk, pv, pwl, pa, pr, phv, vfirst, k_k, k_a, r_k, pat, pbt, prks);
    scan_kernel  <<<128, 256>>>(pr, pwl, pk, pv, pat, pbt, py, stateOut);
    gn_kernel    <<<BT_, 512>>>(py, pv, pg, prks, gsc, gbi);

    TCParams Pout;
    Pout.s[0].ahi = pzhi; Pout.s[0].alo = pzlo;
    Pout.s[0].bhi = pwhiT + (size_t)3*1024*1024;
    Pout.s[0].blo = pwloT + (size_t)3*1024*1024;
    Pout.s[0].c   = out;
    Pout.s[1] = Pout.s[0]; Pout.s[2] = Pout.s[0];
    mma_gemm<<<dim3(8,32,1), 256, MMA_SMEM_BYTES>>>(Pout);

    if (out_size >= YN + SN + YN)
        cudaMemcpyAsync(out + YN + SN, vfirst, (size_t)YN*sizeof(float),
                        cudaMemcpyDeviceToDevice, 0);
}

// round 6
// speedup vs baseline: 2.0222x; 1.0848x over previous
#include <cuda_runtime.h>
#include <cuda_bf16.h>
#include <math.h>
#include <stdint.h>

#define B_ 4
#define T_ 1024
#define D_ 1024
#define H_ 16
#define HS_ 64
#define BT_ (B_*T_)
#define DECAY_C (-0.606531f)

// ---------------- scratch ----------------
__device__ float g_r  [BT_*D_];
__device__ float g_wl [BT_*D_];
__device__ float g_k  [BT_*D_];
__device__ float g_v  [BT_*D_];
__device__ float g_a  [BT_*D_];
__device__ float g_g  [BT_*D_];
__device__ float g_at [BT_*D_];
__device__ float g_bt [BT_*D_];
__device__ float g_hv [BT_*D_];
__device__ float g_rks[BT_*H_];
__device__ float g_y  [BT_*D_];
__device__ float g_ds [B_*H_*HS_*HS_];

// bf16 split operands
__device__ __align__(16) __nv_bfloat16 g_whiT[4][1024*1024];  // big W^T hi (rw,kw,vw,outW)
__device__ __align__(16) __nv_bfloat16 g_wloT[4][1024*1024];
__device__ __align__(16) __nv_bfloat16 g_ahi[6][BT_*D_];      // mixed activations hi (lam rows 0..5)
__device__ __align__(16) __nv_bfloat16 g_alo[6][BT_*D_];
__device__ __align__(16) __nv_bfloat16 g_zhi[BT_*D_];
__device__ __align__(16) __nv_bfloat16 g_zlo[BT_*D_];

// LoRA weight splits (zero-init; pad regions never written -> stay zero)
__device__ __align__(16) __nv_bfloat16 g_l1hi[(64+64+64+128)*1024];  // w1T,a1T,v1T(pad),g1T  [N][1024]
__device__ __align__(16) __nv_bfloat16 g_l1lo[(64+64+64+128)*1024];
__device__ __align__(16) __nv_bfloat16 g_l2hi[1024*(64+64+64+128)];  // w2T,a2T,v2T(pad),g2T  [1024][Kpad]
__device__ __align__(16) __nv_bfloat16 g_l2lo[1024*(64+64+64+128)];
// stage-1 outputs as bf16 hi/lo: hw[4096*64] ha[..64] hv[..64 pad] hg[..128]
__device__ __align__(16) __nv_bfloat16 g_s1hi[BT_*(64+64+64+128)];
__device__ __align__(16) __nv_bfloat16 g_s1lo[BT_*(64+64+64+128)];

// ================= low-level helpers =================
__device__ __forceinline__ uint32_t smem_to_u32(const void* p) {
    uint32_t a;
    asm("{ .reg .u64 t; cvta.to.shared.u64 t, %1; cvt.u32.u64 %0, t; }" : "=r"(a) : "l"(p));
    return a;
}
__device__ __forceinline__ void cpasync16(uint32_t saddr, const void* g) {
    asm volatile("cp.async.cg.shared.global [%0], [%1], 16;" :: "r"(saddr), "l"(g));
}
#define CP_COMMIT() asm volatile("cp.async.commit_group;" ::: "memory")
#define CP_WAIT1()  asm volatile("cp.async.wait_group 1;" ::: "memory")
#define CP_WAIT0()  asm volatile("cp.async.wait_group 0;" ::: "memory")

__device__ __forceinline__ void ldsm4(uint32_t* r, uint32_t addr) {
    asm volatile("ldmatrix.sync.aligned.m8n8.x4.shared.b16 {%0,%1,%2,%3}, [%4];"
                 : "=r"(r[0]), "=r"(r[1]), "=r"(r[2]), "=r"(r[3]) : "r"(addr));
}
__device__ __forceinline__ void ldsm2(uint32_t* r, uint32_t addr) {
    asm volatile("ldmatrix.sync.aligned.m8n8.x2.shared.b16 {%0,%1}, [%2];"
                 : "=r"(r[0]), "=r"(r[1]) : "r"(addr));
}
__device__ __forceinline__ void mma16816(float* d, const uint32_t* a, const uint32_t* b) {
    asm volatile("mma.sync.aligned.m16n8k16.row.col.f32.bf16.bf16.f32 "
                 "{%0,%1,%2,%3}, {%4,%5,%6,%7}, {%8,%9}, {%0,%1,%2,%3};"
                 : "+f"(d[0]), "+f"(d[1]), "+f"(d[2]), "+f"(d[3])
                 : "r"(a[0]), "r"(a[1]), "r"(a[2]), "r"(a[3]), "r"(b[0]), "r"(b[1]));
}
__device__ __forceinline__ void split_bf(float x, __nv_bfloat16& h, __nv_bfloat16& l) {
    h = __float2bfloat16(x);
    l = __float2bfloat16(x - __bfloat162float(h));
}
__device__ __forceinline__ float actf(float v, int act) {
    if (act == 1) return tanhf(v);
    if (act == 2) return 1.f / (1.f + expf(-v));
    return v;
}

// ================= transpose + split (all 12 weights) =================
struct TSJob { const float* W; int K, N; __nv_bfloat16 *hi, *lo; int stride; };
struct TSParams { TSJob j[12]; };

__global__ __launch_bounds__(256) void tsplit_kernel(TSParams P)
{
    TSJob J = P.j[blockIdx.z];
    int k0 = blockIdx.y*32, n0 = blockIdx.x*32;
    if (k0 >= J.K || n0 >= J.N) return;
    __shared__ float ts[32][33];
    int tx = threadIdx.x & 31, ty = threadIdx.x >> 5;
    #pragma unroll
    for (int i = 0; i < 4; i++)
        ts[ty+i*8][tx] = J.W[(size_t)(k0+ty+i*8)*J.N + n0+tx];
    __syncthreads();
    #pragma unroll
    for (int i = 0; i < 4; i++) {
        int r = ty + i*8;
        float v = ts[tx][r];
        __nv_bfloat16 h, l; split_bf(v, h, l);
        J.hi[(size_t)(n0+r)*J.stride + k0+tx] = h;
        J.lo[(size_t)(n0+r)*J.stride + k0+tx] = l;
    }
}

// ================= activation mix + split (6 branches) =================
__global__ __launch_bounds__(256) void asplit_kernel(
    const float* __restrict__ cur, const float* __restrict__ prev,
    const float* __restrict__ lam)
{
    int z = blockIdx.y;
    const float* lr = lam + z*D_;
    __nv_bfloat16* hi = g_ahi[z];
    __nv_bfloat16* lo = g_alo[z];
    size_t e = ((size_t)blockIdx.x*256 + threadIdx.x)*4;
    float4 c = *(const float4*)(cur+e);
    float4 p = *(const float4*)(prev+e);
    int col = (int)(e & 1023);
    float4 l4 = *(const float4*)(lr+col);
    float m0 = fmaf(l4.x, p.x-c.x, c.x), m1 = fmaf(l4.y, p.y-c.y, c.y);
    float m2 = fmaf(l4.z, p.z-c.z, c.z), m3 = fmaf(l4.w, p.w-c.w, c.w);
    __nv_bfloat16 h0,l0,h1,l1,h2,l2,h3,l3;
    split_bf(m0,h0,l0); split_bf(m1,h1,l1); split_bf(m2,h2,l2); split_bf(m3,h3,l3);
    __nv_bfloat162* hp = (__nv_bfloat162*)(hi+e);
    __nv_bfloat162* lp = (__nv_bfloat162*)(lo+e);
    hp[0] = __nv_bfloat162(h0,h1); hp[1] = __nv_bfloat162(h2,h3);
    lp[0] = __nv_bfloat162(l0,l1); lp[1] = __nv_bfloat162(l2,l3);
}

// ================= HMMA split-bf16 GEMM, BN=128, runtime lda/ldb/K =================
struct MJob { const __nv_bfloat16 *ahi, *alo, *bhi, *blo; int lda, ldb, K;
              const float* bias; int act; float* c; };
struct MParams { MJob s[4]; };

#define MMA_STRIDE 40
#define TILE_ELE (128*MMA_STRIDE)
#define MMA_SMEM_BYTES (2*4*TILE_ELE*2)

__global__ __launch_bounds__(256,2) void mma_gemm(MParams P)
{
    extern __shared__ __align__(16) __nv_bfloat16 sm[];
    const uint32_t smb = smem_to_u32(sm);
    MJob S = P.s[blockIdx.z];
    const int tid = threadIdx.x, lane = tid & 31, w = tid >> 5;
    const int wm = w & 3, wn = w >> 2;
    const int brow = blockIdx.y * 128, bcol = blockIdx.x * 128;
    const int lda = S.lda, ldb = S.ldb;

    const __nv_bfloat16* gA0 = S.ahi + (size_t)brow*lda;
    const __nv_bfloat16* gA1 = S.alo + (size_t)brow*lda;
    const __nv_bfloat16* gB0 = S.bhi + (size_t)bcol*ldb;
    const __nv_bfloat16* gB1 = S.blo + (size_t)bcol*ldb;

    auto issue = [&](int c) {
        const int st = c & 1;
        const int r = tid >> 2, q = tid & 3;
        const int r2 = r + 64;
        const size_t ka = (size_t)c*32 + q*8;
        #pragma unroll
        for (int hl = 0; hl < 2; hl++) {
            const __nv_bfloat16* gA = hl ? gA1 : gA0;
            const __nv_bfloat16* gB = hl ? gB1 : gB0;
            uint32_t base = smb + 2u*((uint32_t)(st*4 + hl)*TILE_ELE);
            cpasync16(base + 2u*(r *MMA_STRIDE + q*8), gA + (size_t)r *lda + ka);
            cpasync16(base + 2u*(r2*MMA_STRIDE + q*8), gA + (size_t)r2*lda + ka);
            base = smb + 2u*((uint32_t)(st*4 + 2 + hl)*TILE_ELE);
            cpasync16(base + 2u*(r *MMA_STRIDE + q*8), gB + (size_t)r *ldb + ka);
            cpasync16(base + 2u*(r2*MMA_STRIDE + q*8), gB + (size_t)r2*ldb + ka);
        }
    };

    float acc[2][8][4];
    #pragma unroll
    for (int mi = 0; mi < 2; mi++)
        #pragma unroll
        for (int ni = 0; ni < 8; ni++)
            #pragma unroll
            for (int q = 0; q < 4; q++) acc[mi][ni][q] = 0.f;

    const int la15 = lane & 15;
    const int akc  = (lane >> 4) << 3;
    const int tt   = lane & 15;
    const int bro  = tt & 7;
    const int bkc  = (tt >> 3) << 3;

    const int nC = S.K >> 5;
    issue(0); CP_COMMIT();

    for (int c = 0; c < nC; c++) {
        if (c + 1 < nC) { issue(c + 1); CP_COMMIT(); CP_WAIT1(); }
        else            { CP_WAIT0(); }
        __syncthreads();

        const uint32_t stb = smb + 2u*(uint32_t)((c & 1)*4)*TILE_ELE;
        #pragma unroll
        for (int ks = 0; ks < 32; ks += 16) {
            uint32_t ah[2][4], al[2][4];
            #pragma unroll
            for (int mi = 0; mi < 2; mi++) {
                const int row = wm*32 + mi*16 + la15;
                const uint32_t ao = 2u*(row*MMA_STRIDE + ks + akc);
                ldsm4(ah[mi], stb + 0*2*TILE_ELE + ao);
                ldsm4(al[mi], stb + 1*2*TILE_ELE + ao);
            }
            #pragma unroll
            for (int ni = 0; ni < 8; ni++) {
                const int nrow = wn*64 + ni*8 + bro;
                const uint32_t bo = 2u*(nrow*MMA_STRIDE + ks + bkc);
                uint32_t bh[2], bl[2];
                ldsm2(bh, stb + 2*2*TILE_ELE + bo);
                ldsm2(bl, stb + 3*2*TILE_ELE + bo);
                #pragma unroll
                for (int mi = 0; mi < 2; mi++) {
                    mma16816(acc[mi][ni], ah[mi], bh);
                    mma16816(acc[mi][ni], ah[mi], bl);
                    mma16816(acc[mi][ni], al[mi], bh);
                }
            }
        }
        __syncthreads();
    }

    const int g2 = lane >> 2, cc = lane & 3;
    #pragma unroll
    for (int mi = 0; mi < 2; mi++) {
        #pragma unroll
        for (int ni = 0; ni < 8; ni++) {
            const int row = brow + wm*32 + mi*16;
            const int col = bcol + wn*64 + ni*8 + 2*cc;
            float b0 = 0.f, b1 = 0.f;
            if (S.bias) { b0 = S.bias[col]; b1 = S.bias[col+1]; }
            float v0 = actf(acc[mi][ni][0] + b0, S.act);
            float v1 = actf(acc[mi][ni][1] + b1, S.act);
            float v2 = actf(acc[mi][ni][2] + b0, S.act);
            float v3 = actf(acc[mi][ni][3] + b1, S.act);
            *(float2*)(S.c + (size_t)(row + g2    )*1024 + col) = make_float2(v0, v1);
            *(float2*)(S.c + (size_t)(row + g2 + 8)*1024 + col) = make_float2(v2, v3);
        }
    }
}

// ================= HMMA split-bf16 GEMM, BN=64 (LoRA stage-1) =================
// Epilogue: activation + bf16 split, written to stage-1 hi/lo buffers.
struct LJob { const __nv_bfloat16 *ahi, *alo, *bhi, *blo; int act;
              __nv_bfloat16 *ohi, *olo; int ostride, ocol; };
struct LParams { LJob s[5]; };

#define L_SA (128*MMA_STRIDE)
#define L_SB (64*MMA_STRIDE)
#define L_STAGE (2*L_SA + 2*L_SB)
#define L_SMEM_BYTES (2*L_STAGE*2)

__global__ __launch_bounds__(256,2) void mma_lora1(LParams P)
{
    extern __shared__ __align__(16) __nv_bfloat16 sm[];
    const uint32_t smb = smem_to_u32(sm);
    LJob S = P.s[blockIdx.z];
    const int tid = threadIdx.x, lane = tid & 31, w = tid >> 5;
    const int wm = w & 3, wn = w >> 2;           // 4 m-tiles x 2 n-tiles (32x32 warp tile)
    const int brow = blockIdx.y * 128;

    const __nv_bfloat16* gA0 = S.ahi + (size_t)brow*1024;
    const __nv_bfloat16* gA1 = S.alo + (size_t)brow*1024;

    auto issue = [&](int c) {
        const int st = c & 1;
        const uint32_t sbase = smb + 2u*(uint32_t)(st*L_STAGE);
        {   // A: 128x32, 2 cp per thread per hi/lo
            const int r = tid >> 2, q = tid & 3, r2 = r + 64;
            const size_t ka = (size_t)c*32 + q*8;
            cpasync16(sbase + 2u*(r *MMA_STRIDE + q*8),          gA0 + (size_t)r *1024 + ka);
            cpasync16(sbase + 2u*(r2*MMA_STRIDE + q*8),          gA0 + (size_t)r2*1024 + ka);
            cpasync16(sbase + 2u*(L_SA + r *MMA_STRIDE + q*8),   gA1 + (size_t)r *1024 + ka);
            cpasync16(sbase + 2u*(L_SA + r2*MMA_STRIDE + q*8),   gA1 + (size_t)r2*1024 + ka);
        }
        {   // B: 64x32, 1 cp per thread per hi/lo
            const int r = tid >> 2, q = tid & 3;
            const size_t ka = (size_t)c*32 + q*8;
            cpasync16(sbase + 2u*(2*L_SA + r*MMA_STRIDE + q*8),        S.bhi + (size_t)r*1024 + ka);
            cpasync16(sbase + 2u*(2*L_SA + L_SB + r*MMA_STRIDE + q*8), S.blo + (size_t)r*1024 + ka);
        }
    };

    float acc[2][4][4];
    #pragma unroll
    for (int mi = 0; mi < 2; mi++)
        #pragma unroll
        for (int ni = 0; ni < 4; ni++)
            #pragma unroll
            for (int q = 0; q < 4; q++) acc[mi][ni][q] = 0.f;

    const int la15 = lane & 15;
    const int akc  = (lane >> 4) << 3;
    const int tt   = lane & 15;
    const int bro  = tt & 7;
    const int bkc  = (tt >> 3) << 3;

    issue(0); CP_COMMIT();
    for (int c = 0; c < 32; c++) {
        if (c + 1 < 32) { issue(c + 1); CP_COMMIT(); CP_WAIT1(); }
        else            { CP_WAIT0(); }
        __syncthreads();

        const uint32_t stb = smb + 2u*(uint32_t)((c & 1)*L_STAGE);
        #pragma unroll
        for (int ks = 0; ks < 32; ks += 16) {
            uint32_t ah[2][4], al[2][4];
            #pragma unroll
            for (int mi = 0; mi < 2; mi++) {
                const int row = wm*32 + mi*16 + la15;
                const uint32_t ao = 2u*(row*MMA_STRIDE + ks + akc);
                ldsm4(ah[mi], stb + ao);
                ldsm4(al[mi], stb + 2u*L_SA + ao);
            }
            #pragma unroll
            for (int ni = 0; ni < 4; ni++) {
                const int nrow = wn*32 + ni*8 + bro;
                const uint32_t bo = 2u*(nrow*MMA_STRIDE + ks + bkc);
                uint32_t bh[2], bl[2];
                ldsm2(bh, stb + 2u*(2*L_SA) + bo);
                ldsm2(bl, stb + 2u*(2*L_SA + L_SB) + bo);
                #pragma unroll
                for (int mi = 0; mi < 2; mi++) {
                    mma16816(acc[mi][ni], ah[mi], bh);
                    mma16816(acc[mi][ni], ah[mi], bl);
                    mma16816(acc[mi][ni], al[mi], bh);
                }
            }
        }
        __syncthreads();
    }

    const int g2 = lane >> 2, cc = lane & 3;
    #pragma unroll
    for (int mi = 0; mi < 2; mi++) {
        #pragma unroll
        for (int ni = 0; ni < 4; ni++) {
            const int row = brow + wm*32 + mi*16;
            const int col = S.ocol + wn*32 + ni*8 + 2*cc;
            #pragma unroll
            for (int half = 0; half < 2; half++) {
                float v0 = actf(acc[mi][ni][half*2+0], S.act);
                float v1 = actf(acc[mi][ni][half*2+1], S.act);
                __nv_bfloat16 h0,l0,h1,l1;
                split_bf(v0,h0,l0); split_bf(v1,h1,l1);
                size_t o = (size_t)(row + g2 + half*8)*S.ostride + col;
                *(__nv_bfloat162*)(S.ohi + o) = __nv_bfloat162(h0,h1);
                *(__nv_bfloat162*)(S.olo + o) = __nv_bfloat162(l0,l1);
            }
        }
    }
}

// ---------------- post ----------------
__launch_bounds__(512)
__global__ void post_kernel(float* __restrict__ K_, float* __restrict__ V_,
    float* __restrict__ WL, const float* __restrict__ A_, const float* __restrict__ R_,
    const float* __restrict__ HV, const float* __restrict__ vfirst,
    const float* __restrict__ kkv, const float* __restrict__ kav, const float* __restrict__ rkv,
    float* __restrict__ AT, float* __restrict__ BTt, float* __restrict__ RKS)
{
    int bt = blockIdx.x;
    int h = threadIdx.x >> 5, lane = threadIdx.x & 31;
    int base = bt * D_ + h * HS_;
    int ce0 = h*HS_ + lane, ce1 = ce0 + 32;
    int i0 = base + lane, i1 = i0 + 32;

    float k0 = K_[i0], k1 = K_[i1];
    float kk0 = k0 * kkv[ce0], kk1 = k1 * kkv[ce1];
    float n2 = kk0*kk0 + kk1*kk1;
    #pragma unroll
    for (int o = 16; o; o >>= 1) n2 += __shfl_xor_sync(0xffffffffu, n2, o);
    float inv = rsqrtf(n2);
    kk0 *= inv; kk1 *= inv;

    float a0 = A_[i0], a1 = A_[i1];
    AT[i0] = -kk0;      AT[i1] = -kk1;
    BTt[i0] = kk0 * a0; BTt[i1] = kk1 * a1;

    k0 *= 1.f + (a0 - 1.f) * kav[ce0];
    k1 *= 1.f + (a1 - 1.f) * kav[ce1];
    K_[i0] = k0; K_[i1] = k1;

    float v0 = V_[i0], v1 = V_[i1];
    float hg0 = HV[i0], hg1 = HV[i1];
    v0 += (vfirst[i0] - v0) * hg0;
    v1 += (vfirst[i1] - v1) * hg1;
    V_[i0] = v0; V_[i1] = v1;

    float w0 = WL[i0], w1 = WL[i1];
    WL[i0] = expf(DECAY_C / (1.f + expf(-w0)));
    WL[i1] = expf(DECAY_C / (1.f + expf(-w1)));

    float rs = R_[i0]*k0*rkv[ce0] + R_[i1]*k1*rkv[ce1];
    #pragma unroll
    for (int o = 16; o; o >>= 1) rs += __shfl_xor_sync(0xffffffffu, rs, o);
    if (lane == 0) RKS[bt*H_ + h] = rs;
}

// ---------------- scan ----------------
#define LOAD8(dst, ptr) do { \
    float4 u0 = *(const float4*)(ptr); float4 u1 = *(const float4*)((ptr)+4); \
    dst[0]=u0.x; dst[1]=u0.y; dst[2]=u0.z; dst[3]=u0.w; \
    dst[4]=u1.x; dst[5]=u1.y; dst[6]=u1.z; dst[7]=u1.w; } while(0)

__launch_bounds__(256)
__global__ void scan_kernel(const float* __restrict__ R_, const float* __restrict__ W_,
    const float* __restrict__ K_, const float* __restrict__ V_,
    const float* __restrict__ AT, const float* __restrict__ BTt,
    float* __restrict__ Y, float* __restrict__ S)
{
    __shared__ float4 vbuf[2][88];
    __shared__ float redA[8][32];
    __shared__ float redY[8][32];
    int bid = blockIdx.x;
    int b = bid >> 5; int rem = bid & 31; int h = rem >> 1; int half = rem & 1;
    int tid = threadIdx.x;
    int kg = tid >> 5, vl = tid & 31;
    int kb = kg * 8;

    const float* msrc = nullptr;
    if (tid < 88) {
        const float* bp; int inner;
        if (tid < 80) {
            int arr = tid / 16, q = tid % 16;
            bp = (arr==0) ? AT : (arr==1) ? W_ : (arr==2) ? BTt : (arr==3) ? K_ : R_;
            inner = q * 4;
        } else {
            bp = V_; inner = half*32 + (tid - 80) * 4;
        }
        msrc = bp + h*HS_ + inner;
    }

    float s[8];
    #pragma unroll
    for (int i = 0; i < 8; i++) s[i] = 0.f;

    size_t row0 = (size_t)b * T_ * D_;
    if (tid < 88) vbuf[0][tid] = *(const float4*)(msrc + row0);
    __syncthreads();

    for (int t = 0; t < T_; t++) {
        int cb = t & 1;
        if (tid < 88 && t + 1 < T_)
            vbuf[cb^1][tid] = *(const float4*)(msrc + row0 + (size_t)(t+1) * D_);

        const float* base = (const float*)vbuf[cb];
        const float* at_ = base;
        const float* w_  = base + 64;
        const float* bt_ = base + 128;
        const float* k_  = base + 192;
        const float* r_  = base + 256;
        const float* vv  = base + 320;

        float atr[8], wr[8], btr[8], kr[8], rr[8];
        LOAD8(atr, at_ + kb); LOAD8(wr, w_ + kb); LOAD8(btr, bt_ + kb);
        LOAD8(kr,  k_  + kb); LOAD8(rr, r_ + kb);
        float vt = vv[vl];

        float p = 0.f;
        #pragma unroll
        for (int i = 0; i < 8; i++) p += s[i] * atr[i];
        redA[kg][vl] = p;
        __syncthreads();

        float sa = 0.f;
        #pragma unroll
        for (int g2 = 0; g2 < 8; g2++) sa += redA[g2][vl];

        float y = 0.f;
        #pragma unroll
        for (int i = 0; i < 8; i++) {
            float sn = s[i]*wr[i] + sa*btr[i] + vt*kr[i];
            s[i] = sn;
            y += sn * rr[i];
        }
        redY[kg][vl] = y;
        __syncthreads();

        if (kg == 0) {
            float yy = 0.f;
            #pragma unroll
            for (int g2 = 0; g2 < 8; g2++) yy += redY[g2][vl];
            Y[row0 + (size_t)t*D_ + h*HS_ + half*32 + vl] = yy;
        }
    }
    int v = half*32 + vl;
    size_t sb2 = ((size_t)(b*H_ + h)*HS_ + v)*HS_ + kb;
    *(float4*)(S + sb2)     = make_float4(s[0], s[1], s[2], s[3]);
    *(float4*)(S + sb2 + 4) = make_float4(s[4], s[5], s[6], s[7]);
}

// ---------------- groupnorm + residual + gate + bf16 split ----------------
__launch_bounds__(512)
__global__ void gn_kernel(const float* __restrict__ Y, const float* __restrict__ V_,
    const float* __restrict__ G_, const float* __restrict__ RKS,
    const float* __restrict__ gsc, const float* __restrict__ gbi)
{
    int bt = blockIdx.x;
    int h = threadIdx.x >> 5, lane = threadIdx.x & 31;
    int base = bt * D_ + h * HS_;
    int i0 = base + lane, i1 = i0 + 32;
    int ce0 = h*HS_ + lane, ce1 = ce0 + 32;
    float y0 = Y[i0], y1 = Y[i1];
    float sm = y0 + y1, sq = y0*y0 + y1*y1;
    #pragma unroll
    for (int o = 16; o; o >>= 1) {
        sm += __shfl_xor_sync(0xffffffffu, sm, o);
        sq += __shfl_xor_sync(0xffffffffu, sq, o);
    }
    float mu  = sm * (1.f/64.f);
    float var = sq * (1.f/64.f) - mu*mu;
    float inv = rsqrtf(var + 1e-5f);
    float rk  = RKS[bt*H_ + h];
    float o0 = ((y0 - mu)*inv*gsc[ce0] + gbi[ce0] + rk*V_[i0]) * G_[i0];
    float o1 = ((y1 - mu)*inv*gsc[ce1] + gbi[ce1] + rk*V_[i1]) * G_[i1];
    __nv_bfloat16 h0,l0,h1,l1;
    split_bf(o0, h0, l0); split_bf(o1, h1, l1);
    g_zhi[i0] = h0; g_zhi[i1] = h1;
    g_zlo[i0] = l0; g_zlo[i1] = l1;
}

// ---------------- launch ----------------
extern "C" void kernel_launch(void* const* d_in, const int* in_sizes, int n_in,
                              void* d_out, int out_size)
{
    const float* cur    = (const float*)d_in[0];
    const float* prev   = (const float*)d_in[1];
    const float* vfirst = (const float*)d_in[2];
    const float* lam    = (const float*)d_in[3];
    const float* rw_W   = (const float*)d_in[4];
    const float* w1     = (const float*)d_in[5];
    const float* w2     = (const float*)d_in[6];
    const float* w2b    = (const float*)d_in[7];
    const float* kw     = (const float*)d_in[8];
    const float* vw     = (const float*)d_in[9];
    const float* a1     = (const float*)d_in[10];
    const float* a2     = (const float*)d_in[11];
    const float* a2b    = (const float*)d_in[12];
    const float* v1     = (const float*)d_in[13];
    const float* v2     = (const float*)d_in[14];
    const float* v2b    = (const float*)d_in[15];
    const float* g1     = (const float*)d_in[16];
    const float* g2     = (const float*)d_in[17];
    const float* g2b    = (const float*)d_in[18];
    const float* k_k    = (const float*)d_in[19];
    const float* k_a    = (const float*)d_in[20];
    const float* r_k    = (const float*)d_in[21];
    const float* gsc    = (const float*)d_in[22];
    const float* gbi    = (const float*)d_in[23];
    const float* outW   = (const float*)d_in[24];
    (void)in_sizes; (void)n_in;

    float *pr,*pwl,*pk,*pv,*pa,*pg,*pat,*pbt,*phv,*prks,*py,*pds;
    cudaGetSymbolAddress((void**)&pr,  g_r);
    cudaGetSymbolAddress((void**)&pwl, g_wl);
    cudaGetSymbolAddress((void**)&pk,  g_k);
    cudaGetSymbolAddress((void**)&pv,  g_v);
    cudaGetSymbolAddress((void**)&pa,  g_a);
    cudaGetSymbolAddress((void**)&pg,  g_g);
    cudaGetSymbolAddress((void**)&pat, g_at);
    cudaGetSymbolAddress((void**)&pbt, g_bt);
    cudaGetSymbolAddress((void**)&phv, g_hv);
    cudaGetSymbolAddress((void**)&prks,g_rks);
    cudaGetSymbolAddress((void**)&py,  g_y);
    cudaGetSymbolAddress((void**)&pds, g_ds);

    __nv_bfloat16 *pwhiT,*pwloT,*pahi,*palo,*pzhi,*pzlo,*pl1h,*pl1l,*pl2h,*pl2l,*ps1h,*ps1l;
    cudaGetSymbolAddress((void**)&pwhiT, g_whiT);
    cudaGetSymbolAddress((void**)&pwloT, g_wloT);
    cudaGetSymbolAddress((void**)&pahi,  g_ahi);
    cudaGetSymbolAddress((void**)&palo,  g_alo);
    cudaGetSymbolAddress((void**)&pzhi,  g_zhi);
    cudaGetSymbolAddress((void**)&pzlo,  g_zlo);
    cudaGetSymbolAddress((void**)&pl1h,  g_l1hi);
    cudaGetSymbolAddress((void**)&pl1l,  g_l1lo);
    cudaGetSymbolAddress((void**)&pl2h,  g_l2hi);
    cudaGetSymbolAddress((void**)&pl2l,  g_l2lo);
    cudaGetSymbolAddress((void**)&ps1h,  g_s1hi);
    cudaGetSymbolAddress((void**)&ps1l,  g_s1lo);

    float* out = (float*)d_out;
    const int YN = BT_*D_;
    const int SN = B_*H_*HS_*HS_;
    float* stateOut = (out_size >= YN + SN) ? (out + YN) : pds;

    cudaFuncSetAttribute(mma_gemm,  cudaFuncAttributeMaxDynamicSharedMemorySize, MMA_SMEM_BYTES);
    cudaFuncSetAttribute(mma_lora1, cudaFuncAttributeMaxDynamicSharedMemorySize, L_SMEM_BYTES);

    // offsets into lora weight split buffers (elements)
    const size_t O_W1 = 0, O_A1 = 64*1024, O_V1 = 128*1024, O_G1 = 192*1024; // l1: [N][1024]
    const size_t P_W2 = 0, P_A2 = 1024*64, P_V2 = 2*1024*64, P_G2 = 3*1024*64; // l2: [1024][Kpad]
    const size_t S_HW = 0, S_HA = (size_t)BT_*64, S_HV = (size_t)BT_*128, S_HG = (size_t)BT_*192;

    // 12 transpose+split jobs
    TSParams TP;
    TP.j[0]  = { rw_W, 1024, 1024, pwhiT + 0*1024*1024, pwloT + 0*1024*1024, 1024 };
    TP.j[1]  = { kw,   1024, 1024, pwhiT + 1*1024*1024, pwloT + 1*1024*1024, 1024 };
    TP.j[2]  = { vw,   1024, 1024, pwhiT + 2*1024*1024, pwloT + 2*1024*1024, 1024 };
    TP.j[3]  = { outW, 1024, 1024, pwhiT + 3*1024*1024, pwloT + 3*1024*1024, 1024 };
    TP.j[4]  = { w1, 1024,  64, pl1h + O_W1, pl1l + O_W1, 1024 };
    TP.j[5]  = { a1, 1024,  64, pl1h + O_A1, pl1l + O_A1, 1024 };
    TP.j[6]  = { v1, 1024,  32, pl1h + O_V1, pl1l + O_V1, 1024 };
    TP.j[7]  = { g1, 1024, 128, pl1h + O_G1, pl1l + O_G1, 1024 };
    TP.j[8]  = { w2,  64, 1024, pl2h + P_W2, pl2l + P_W2,  64 };
    TP.j[9]  = { a2,  64, 1024, pl2h + P_A2, pl2l + P_A2,  64 };
    TP.j[10] = { v2,  32, 1024, pl2h + P_V2, pl2l + P_V2,  64 };
    TP.j[11] = { g2, 128, 1024, pl2h + P_G2, pl2l + P_G2, 128 };
    tsplit_kernel<<<dim3(32,32,12), 256>>>(TP);
    asplit_kernel<<<dim3(4096,6),   256>>>(cur, prev, lam);

    // big r/k/v projections (branches 0,2,3)
    MParams Prkv;
    {
        const int br[3] = {0, 2, 3};
        float* cs[3] = {pr, pk, pv};
        for (int z = 0; z < 3; z++) {
            Prkv.s[z] = { pahi + (size_t)br[z]*BT_*D_, palo + (size_t)br[z]*BT_*D_,
                          pwhiT + (size_t)z*1024*1024, pwloT + (size_t)z*1024*1024,
                          1024, 1024, 1024, nullptr, 0, cs[z] };
        }
        Prkv.s[3] = Prkv.s[0];
    }
    mma_gemm<<<dim3(8,32,3), 256, MMA_SMEM_BYTES>>>(Prkv);

    // LoRA stage-1 (branches: w=1, a=4, v=3, g=5)
    LParams LP;
    LP.s[0] = { pahi + (size_t)1*BT_*D_, palo + (size_t)1*BT_*D_, pl1h+O_W1, pl1l+O_W1, 1, ps1h+S_HW, ps1l+S_HW,  64, 0 };
    LP.s[1] = { pahi + (size_t)4*BT_*D_, palo + (size_t)4*BT_*D_, pl1h+O_A1, pl1l+O_A1, 0, ps1h+S_HA, ps1l+S_HA,  64, 0 };
    LP.s[2] = { pahi + (size_t)3*BT_*D_, palo + (size_t)3*BT_*D_, pl1h+O_V1, pl1l+O_V1, 0, ps1h+S_HV, ps1l+S_HV,  64, 0 };
    LP.s[3] = { pahi + (size_t)5*BT_*D_, palo + (size_t)5*BT_*D_, pl1h+O_G1,          pl1l+O_G1,          2, ps1h+S_HG, ps1l+S_HG, 128, 0 };
    LP.s[4] = { pahi + (size_t)5*BT_*D_, palo + (size_t)5*BT_*D_, pl1h+O_G1+64*1024,  pl1l+O_G1+64*1024,  2, ps1h+S_HG, ps1l+S_HG, 128, 64 };
    mma_lora1<<<dim3(1,32,5), 256, L_SMEM_BYTES>>>(LP);

    // LoRA stage-2
    MParams P2;
    P2.s[0] = { ps1h+S_HW, ps1l+S_HW, pl2h+P_W2, pl2l+P_W2,  64,  64,  64, w2b, 0, pwl };
    P2.s[1] = { ps1h+S_HA, ps1l+S_HA, pl2h+P_A2, pl2l+P_A2,  64,  64,  64, a2b, 2, pa  };
    P2.s[2] = { ps1h+S_HV, ps1l+S_HV, pl2h+P_V2, pl2l+P_V2,  64,  64,  64, v2b, 2, phv };
    P2.s[3] = { ps1h+S_HG, ps1l+S_HG, pl2h+P_G2, pl2l+P_G2, 128, 128, 128, g2b, 0, pg  };
    mma_gemm<<<dim3(8,32,4), 256, MMA_SMEM_BYTES>>>(P2);

    post_kernel<<<BT_, 512>>>(pk, pv, pwl, pa, pr, phv, vfirst, k_k, k_a, r_k, pat, pbt, prks);
    scan_kernel<<<128, 256>>>(pr, pwl, pk, pv, pat, pbt, py, stateOut);
    gn_kernel  <<<BT_, 512>>>(py, pv, pg, prks, gsc, gbi);

    MParams Pout;
    Pout.s[0] = { pzhi, pzlo, pwhiT + (size_t)3*1024*1024, pwloT + (size_t)3*1024*1024,
                  1024, 1024, 1024, nullptr, 0, out };
    Pout.s[1] = Pout.s[0]; Pout.s[2] = Pout.s[0]; Pout.s[3] = Pout.s[0];
    mma_gemm<<<dim3(8,32,1), 256, MMA_SMEM_BYTES>>>(Pout);

    if (out_size >= YN + SN + YN)
        cudaMemcpyAsync(out + YN + SN, vfirst, (size_t)YN*sizeof(float),
                        cudaMemcpyDeviceToDevice, 0);
}

// round 7
// speedup vs baseline: 2.0573x; 1.0174x over previous
#include <cuda_runtime.h>
#include <cuda_bf16.h>
#include <math.h>
#include <stdint.h>

#define B_ 4
#define T_ 1024
#define D_ 1024
#define H_ 16
#define HS_ 64
#define BT_ (B_*T_)
#define DECAY_C (-0.606531f)

// ---------------- scratch ----------------
__device__ float g_r  [BT_*D_];
__device__ float g_wl [BT_*D_];
__device__ float g_k  [BT_*D_];
__device__ float g_v  [BT_*D_];
__device__ float g_a  [BT_*D_];
__device__ float g_g  [BT_*D_];
__device__ float g_at [BT_*D_];
__device__ float g_bt [BT_*D_];
__device__ float g_hv [BT_*D_];
__device__ float g_rks[BT_*H_];
__device__ float g_y  [BT_*D_];
__device__ float g_ds [B_*H_*HS_*HS_];

// bf16 split operands
__device__ __align__(16) __nv_bfloat16 g_whiT[4][1024*1024];
__device__ __align__(16) __nv_bfloat16 g_wloT[4][1024*1024];
__device__ __align__(16) __nv_bfloat16 g_ahi[6][BT_*D_];
__device__ __align__(16) __nv_bfloat16 g_alo[6][BT_*D_];
__device__ __align__(16) __nv_bfloat16 g_zhi[BT_*D_];
__device__ __align__(16) __nv_bfloat16 g_zlo[BT_*D_];

// LoRA weight splits (zero-init; pads never written)
__device__ __align__(16) __nv_bfloat16 g_l1hi[(64+64+64+128)*1024];
__device__ __align__(16) __nv_bfloat16 g_l1lo[(64+64+64+128)*1024];
__device__ __align__(16) __nv_bfloat16 g_l2hi[1024*(64+64+64+128)];
__device__ __align__(16) __nv_bfloat16 g_l2lo[1024*(64+64+64+128)];
__device__ __align__(16) __nv_bfloat16 g_s1hi[BT_*(64+64+64+128)];
__device__ __align__(16) __nv_bfloat16 g_s1lo[BT_*(64+64+64+128)];

// ================= low-level helpers =================
__device__ __forceinline__ uint32_t smem_to_u32(const void* p) {
    uint32_t a;
    asm("{ .reg .u64 t; cvta.to.shared.u64 t, %1; cvt.u32.u64 %0, t; }" : "=r"(a) : "l"(p));
    return a;
}
__device__ __forceinline__ void cpasync16(uint32_t saddr, const void* g) {
    asm volatile("cp.async.cg.shared.global [%0], [%1], 16;" :: "r"(saddr), "l"(g));
}
#define CP_COMMIT() asm volatile("cp.async.commit_group;" ::: "memory")
#define CP_WAIT1()  asm volatile("cp.async.wait_group 1;" ::: "memory")
#define CP_WAIT0()  asm volatile("cp.async.wait_group 0;" ::: "memory")

__device__ __forceinline__ void ldsm4(uint32_t* r, uint32_t addr) {
    asm volatile("ldmatrix.sync.aligned.m8n8.x4.shared.b16 {%0,%1,%2,%3}, [%4];"
                 : "=r"(r[0]), "=r"(r[1]), "=r"(r[2]), "=r"(r[3]) : "r"(addr));
}
__device__ __forceinline__ void mma16816(float* d, const uint32_t* a, const uint32_t* b) {
    asm volatile("mma.sync.aligned.m16n8k16.row.col.f32.bf16.bf16.f32 "
                 "{%0,%1,%2,%3}, {%4,%5,%6,%7}, {%8,%9}, {%0,%1,%2,%3};"
                 : "+f"(d[0]), "+f"(d[1]), "+f"(d[2]), "+f"(d[3])
                 : "r"(a[0]), "r"(a[1]), "r"(a[2]), "r"(a[3]), "r"(b[0]), "r"(b[1]));
}
__device__ __forceinline__ void split_bf(float x, __nv_bfloat16& h, __nv_bfloat16& l) {
    h = __float2bfloat16(x);
    l = __float2bfloat16(x - __bfloat162float(h));
}
__device__ __forceinline__ float actf(float v, int act) {
    if (act == 1) return tanhf(v);
    if (act == 2) return 1.f / (1.f + expf(-v));
    return v;
}

// ================= transpose + split =================
struct TSJob { const float* W; int K, N; __nv_bfloat16 *hi, *lo; int stride; };
struct TSParams { TSJob j[12]; };

__global__ __launch_bounds__(256) void tsplit_kernel(TSParams P)
{
    TSJob J = P.j[blockIdx.z];
    int k0 = blockIdx.y*32, n0 = blockIdx.x*32;
    if (k0 >= J.K || n0 >= J.N) return;
    __shared__ float ts[32][33];
    int tx = threadIdx.x & 31, ty = threadIdx.x >> 5;
    #pragma unroll
    for (int i = 0; i < 4; i++)
        ts[ty+i*8][tx] = J.W[(size_t)(k0+ty+i*8)*J.N + n0+tx];
    __syncthreads();
    #pragma unroll
    for (int i = 0; i < 4; i++) {
        int r = ty + i*8;
        float v = ts[tx][r];
        __nv_bfloat16 h, l; split_bf(v, h, l);
        J.hi[(size_t)(n0+r)*J.stride + k0+tx] = h;
        J.lo[(size_t)(n0+r)*J.stride + k0+tx] = l;
    }
}

// ================= activation mix + split =================
__global__ __launch_bounds__(256) void asplit_kernel(
    const float* __restrict__ cur, const float* __restrict__ prev,
    const float* __restrict__ lam)
{
    int z = blockIdx.y;
    const float* lr = lam + z*D_;
    __nv_bfloat16* hi = g_ahi[z];
    __nv_bfloat16* lo = g_alo[z];
    size_t e = ((size_t)blockIdx.x*256 + threadIdx.x)*4;
    float4 c = *(const float4*)(cur+e);
    float4 p = *(const float4*)(prev+e);
    int col = (int)(e & 1023);
    float4 l4 = *(const float4*)(lr+col);
    float m0 = fmaf(l4.x, p.x-c.x, c.x), m1 = fmaf(l4.y, p.y-c.y, c.y);
    float m2 = fmaf(l4.z, p.z-c.z, c.z), m3 = fmaf(l4.w, p.w-c.w, c.w);
    __nv_bfloat16 h0,l0,h1,l1,h2,l2,h3,l3;
    split_bf(m0,h0,l0); split_bf(m1,h1,l1); split_bf(m2,h2,l2); split_bf(m3,h3,l3);
    __nv_bfloat162* hp = (__nv_bfloat162*)(hi+e);
    __nv_bfloat162* lp = (__nv_bfloat162*)(lo+e);
    hp[0] = __nv_bfloat162(h0,h1); hp[1] = __nv_bfloat162(h2,h3);
    lp[0] = __nv_bfloat162(l0,l1); lp[1] = __nv_bfloat162(l2,l3);
}

// ================= HMMA split-bf16 GEMM, BM=BN=128 =================
struct MJob { const __nv_bfloat16 *ahi, *alo, *bhi, *blo; int lda, ldb, K;
              const float* bias; int act; float* c; };
struct MParams { MJob s[4]; };

#define MMA_STRIDE 40
#define TILE_ELE (128*MMA_STRIDE)
#define MMA_SMEM_BYTES (2*4*TILE_ELE*2)

__global__ __launch_bounds__(256,2) void mma_gemm(MParams P)
{
    extern __shared__ __align__(16) __nv_bfloat16 sm[];
    const uint32_t smb = smem_to_u32(sm);
    MJob S = P.s[blockIdx.z];
    const int tid = threadIdx.x, lane = tid & 31, w = tid >> 5;
    const int wm = w & 3, wn = w >> 2;
    const int brow = blockIdx.y * 128, bcol = blockIdx.x * 128;
    const int lda = S.lda, ldb = S.ldb;

    const __nv_bfloat16* gA0 = S.ahi + (size_t)brow*lda;
    const __nv_bfloat16* gA1 = S.alo + (size_t)brow*lda;
    const __nv_bfloat16* gB0 = S.bhi + (size_t)bcol*ldb;
    const __nv_bfloat16* gB1 = S.blo + (size_t)bcol*ldb;

    auto issue = [&](int c) {
        const int st = c & 1;
        const int r = tid >> 2, q = tid & 3;
        const int r2 = r + 64;
        const size_t ka = (size_t)c*32 + q*8;
        #pragma unroll
        for (int hl = 0; hl < 2; hl++) {
            const __nv_bfloat16* gA = hl ? gA1 : gA0;
            const __nv_bfloat16* gB = hl ? gB1 : gB0;
            uint32_t base = smb + 2u*((uint32_t)(st*4 + hl)*TILE_ELE);
            cpasync16(base + 2u*(r *MMA_STRIDE + q*8), gA + (size_t)r *lda + ka);
            cpasync16(base + 2u*(r2*MMA_STRIDE + q*8), gA + (size_t)r2*lda + ka);
            base = smb + 2u*((uint32_t)(st*4 + 2 + hl)*TILE_ELE);
            cpasync16(base + 2u*(r *MMA_STRIDE + q*8), gB + (size_t)r *ldb + ka);
            cpasync16(base + 2u*(r2*MMA_STRIDE + q*8), gB + (size_t)r2*ldb + ka);
        }
    };

    float acc[2][8][4];
    #pragma unroll
    for (int mi = 0; mi < 2; mi++)
        #pragma unroll
        for (int ni = 0; ni < 8; ni++)
            #pragma unroll
            for (int q = 0; q < 4; q++) acc[mi][ni][q] = 0.f;

    const int la15 = lane & 15;
    const int akc  = (lane >> 4) << 3;
    // B x4 pairing: lane groups address 2 n-tiles x 2 k-halves
    const int brow16 = ((lane >> 4) << 3) + (lane & 7);   // 0..15 row within pair
    const int bkadd  = ((lane >> 3) & 1) << 3;            // k half

    const int nC = S.K >> 5;
    issue(0); CP_COMMIT();

    for (int c = 0; c < nC; c++) {
        if (c + 1 < nC) { issue(c + 1); CP_COMMIT(); CP_WAIT1(); }
        else            { CP_WAIT0(); }
        __syncthreads();

        const uint32_t stb = smb + 2u*(uint32_t)((c & 1)*4)*TILE_ELE;
        #pragma unroll
        for (int ks = 0; ks < 32; ks += 16) {
            uint32_t ah[2][4], al[2][4];
            #pragma unroll
            for (int mi = 0; mi < 2; mi++) {
                const int row = wm*32 + mi*16 + la15;
                const uint32_t ao = 2u*(row*MMA_STRIDE + ks + akc);
                ldsm4(ah[mi], stb + 0*2*TILE_ELE + ao);
                ldsm4(al[mi], stb + 1*2*TILE_ELE + ao);
            }
            #pragma unroll
            for (int ni2 = 0; ni2 < 4; ni2++) {
                const int nrow = wn*64 + ni2*16 + brow16;
                const uint32_t bo = 2u*(nrow*MMA_STRIDE + ks + bkadd);
                uint32_t bh4[4], bl4[4];
                ldsm4(bh4, stb + 2*2*TILE_ELE + bo);
                ldsm4(bl4, stb + 3*2*TILE_ELE + bo);
                #pragma unroll
                for (int half = 0; half < 2; half++) {
                    const int ni = ni2*2 + half;
                    #pragma unroll
                    for (int mi = 0; mi < 2; mi++) {
                        mma16816(acc[mi][ni], ah[mi], bh4 + half*2);
                        mma16816(acc[mi][ni], ah[mi], bl4 + half*2);
                        mma16816(acc[mi][ni], al[mi], bh4 + half*2);
                    }
                }
            }
        }
        __syncthreads();
    }

    const int g2 = lane >> 2, cc = lane & 3;
    #pragma unroll
    for (int mi = 0; mi < 2; mi++) {
        #pragma unroll
        for (int ni = 0; ni < 8; ni++) {
            const int row = brow + wm*32 + mi*16;
            const int col = bcol + wn*64 + ni*8 + 2*cc;
            float b0 = 0.f, b1 = 0.f;
            if (S.bias) { b0 = S.bias[col]; b1 = S.bias[col+1]; }
            float v0 = actf(acc[mi][ni][0] + b0, S.act);
            float v1 = actf(acc[mi][ni][1] + b1, S.act);
            float v2 = actf(acc[mi][ni][2] + b0, S.act);
            float v3 = actf(acc[mi][ni][3] + b1, S.act);
            *(float2*)(S.c + (size_t)(row + g2    )*1024 + col) = make_float2(v0, v1);
            *(float2*)(S.c + (size_t)(row + g2 + 8)*1024 + col) = make_float2(v2, v3);
        }
    }
}

// ================= HMMA split-bf16 GEMM, BM=64 BN=64 (LoRA stage-1) =================
struct LJob { const __nv_bfloat16 *ahi, *alo, *bhi, *blo; int act;
              __nv_bfloat16 *ohi, *olo; int ostride, ocol; };
struct LParams { LJob s[5]; };

#define L_TILE (64*MMA_STRIDE)
#define L_STAGE (4*L_TILE)
#define L_SMEM_BYTES (2*L_STAGE*2)

__global__ __launch_bounds__(128,4) void mma_lora1(LParams P)
{
    extern __shared__ __align__(16) __nv_bfloat16 sm[];
    const uint32_t smb = smem_to_u32(sm);
    LJob S = P.s[blockIdx.z];
    const int tid = threadIdx.x, lane = tid & 31, w = tid >> 5;
    const int wm = w & 1, wn = w >> 1;           // 2x2 warps, 32x32 warp tile
    const int brow = blockIdx.y * 64;

    const __nv_bfloat16* gA0 = S.ahi + (size_t)brow*1024;
    const __nv_bfloat16* gA1 = S.alo + (size_t)brow*1024;

    auto issue = [&](int c) {
        const int st = c & 1;
        const uint32_t sbase = smb + 2u*(uint32_t)(st*L_STAGE);
        const int r = tid >> 2, q = tid & 3, r2 = r + 32;
        const size_t ka = (size_t)c*32 + q*8;
        cpasync16(sbase + 2u*(r *MMA_STRIDE + q*8),              gA0   + (size_t)r *1024 + ka);
        cpasync16(sbase + 2u*(r2*MMA_STRIDE + q*8),              gA0   + (size_t)r2*1024 + ka);
        cpasync16(sbase + 2u*(L_TILE + r *MMA_STRIDE + q*8),     gA1   + (size_t)r *1024 + ka);
        cpasync16(sbase + 2u*(L_TILE + r2*MMA_STRIDE + q*8),     gA1   + (size_t)r2*1024 + ka);
        cpasync16(sbase + 2u*(2*L_TILE + r *MMA_STRIDE + q*8),   S.bhi + (size_t)r *1024 + ka);
        cpasync16(sbase + 2u*(2*L_TILE + r2*MMA_STRIDE + q*8),   S.bhi + (size_t)r2*1024 + ka);
        cpasync16(sbase + 2u*(3*L_TILE + r *MMA_STRIDE + q*8),   S.blo + (size_t)r *1024 + ka);
        cpasync16(sbase + 2u*(3*L_TILE + r2*MMA_STRIDE + q*8),   S.blo + (size_t)r2*1024 + ka);
    };

    float acc[2][4][4];
    #pragma unroll
    for (int mi = 0; mi < 2; mi++)
        #pragma unroll
        for (int ni = 0; ni < 4; ni++)
            #pragma unroll
            for (int q = 0; q < 4; q++) acc[mi][ni][q] = 0.f;

    const int la15 = lane & 15;
    const int akc  = (lane >> 4) << 3;
    const int brow16 = ((lane >> 4) << 3) + (lane & 7);
    const int bkadd  = ((lane >> 3) & 1) << 3;

    issue(0); CP_COMMIT();
    for (int c = 0; c < 32; c++) {
        if (c + 1 < 32) { issue(c + 1); CP_COMMIT(); CP_WAIT1(); }
        else            { CP_WAIT0(); }
        __syncthreads();

        const uint32_t stb = smb + 2u*(uint32_t)((c & 1)*L_STAGE);
        #pragma unroll
        for (int ks = 0; ks < 32; ks += 16) {
            uint32_t ah[2][4], al[2][4];
            #pragma unroll
            for (int mi = 0; mi < 2; mi++) {
                const int row = wm*32 + mi*16 + la15;
                const uint32_t ao = 2u*(row*MMA_STRIDE + ks + akc);
                ldsm4(ah[mi], stb + ao);
                ldsm4(al[mi], stb + 2u*L_TILE + ao);
            }
            #pragma unroll
            for (int ni2 = 0; ni2 < 2; ni2++) {
                const int nrow = wn*32 + ni2*16 + brow16;
                const uint32_t bo = 2u*(nrow*MMA_STRIDE + ks + bkadd);
                uint32_t bh4[4], bl4[4];
                ldsm4(bh4, stb + 2u*(2*L_TILE) + bo);
                ldsm4(bl4, stb + 2u*(3*L_TILE) + bo);
                #pragma unroll
                for (int half = 0; half < 2; half++) {
                    const int ni = ni2*2 + half;
                    #pragma unroll
                    for (int mi = 0; mi < 2; mi++) {
                        mma16816(acc[mi][ni], ah[mi], bh4 + half*2);
                        mma16816(acc[mi][ni], ah[mi], bl4 + half*2);
                        mma16816(acc[mi][ni], al[mi], bh4 + half*2);
                    }
                }
            }
        }
        __syncthreads();
    }

    const int g2 = lane >> 2, cc = lane & 3;
    #pragma unroll
    for (int mi = 0; mi < 2; mi++) {
        #pragma unroll
        for (int ni = 0; ni < 4; ni++) {
            const int row = brow + wm*32 + mi*16;
            const int col = S.ocol + wn*32 + ni*8 + 2*cc;
            #pragma unroll
            for (int half = 0; half < 2; half++) {
                float v0 = actf(acc[mi][ni][half*2+0], S.act);
                float v1 = actf(acc[mi][ni][half*2+1], S.act);
                __nv_bfloat16 h0,l0,h1,l1;
                split_bf(v0,h0,l0); split_bf(v1,h1,l1);
                size_t o = (size_t)(row + g2 + half*8)*S.ostride + col;
                *(__nv_bfloat162*)(S.ohi + o) = __nv_bfloat162(h0,h1);
                *(__nv_bfloat162*)(S.olo + o) = __nv_bfloat162(l0,l1);
            }
        }
    }
}

// ---------------- post ----------------
__launch_bounds__(512)
__global__ void post_kernel(float* __restrict__ K_, float* __restrict__ V_,
    float* __restrict__ WL, const float* __restrict__ A_, const float* __restrict__ R_,
    const float* __restrict__ HV, const float* __restrict__ vfirst,
    const float* __restrict__ kkv, const float* __restrict__ kav, const float* __restrict__ rkv,
    float* __restrict__ AT, float* __restrict__ BTt, float* __restrict__ RKS)
{
    int bt = blockIdx.x;
    int h = threadIdx.x >> 5, lane = threadIdx.x & 31;
    int base = bt * D_ + h * HS_;
    int ce0 = h*HS_ + lane, ce1 = ce0 + 32;
    int i0 = base + lane, i1 = i0 + 32;

    float k0 = K_[i0], k1 = K_[i1];
    float kk0 = k0 * kkv[ce0], kk1 = k1 * kkv[ce1];
    float n2 = kk0*kk0 + kk1*kk1;
    #pragma unroll
    for (int o = 16; o; o >>= 1) n2 += __shfl_xor_sync(0xffffffffu, n2, o);
    float inv = rsqrtf(n2);
    kk0 *= inv; kk1 *= inv;

    float a0 = A_[i0], a1 = A_[i1];
    AT[i0] = -kk0;      AT[i1] = -kk1;
    BTt[i0] = kk0 * a0; BTt[i1] = kk1 * a1;

    k0 *= 1.f + (a0 - 1.f) * kav[ce0];
    k1 *= 1.f + (a1 - 1.f) * kav[ce1];
    K_[i0] = k0; K_[i1] = k1;

    float v0 = V_[i0], v1 = V_[i1];
    float hg0 = HV[i0], hg1 = HV[i1];
    v0 += (vfirst[i0] - v0) * hg0;
    v1 += (vfirst[i1] - v1) * hg1;
    V_[i0] = v0; V_[i1] = v1;

    float w0 = WL[i0], w1 = WL[i1];
    WL[i0] = expf(DECAY_C / (1.f + expf(-w0)));
    WL[i1] = expf(DECAY_C / (1.f + expf(-w1)));

    float rs = R_[i0]*k0*rkv[ce0] + R_[i1]*k1*rkv[ce1];
    #pragma unroll
    for (int o = 16; o; o >>= 1) rs += __shfl_xor_sync(0xffffffffu, rs, o);
    if (lane == 0) RKS[bt*H_ + h] = rs;
}

// ---------------- scan: ONE barrier per step ----------------
#define LOAD8(dst, ptr) do { \
    float4 u0 = *(const float4*)(ptr); float4 u1 = *(const float4*)((ptr)+4); \
    dst[0]=u0.x; dst[1]=u0.y; dst[2]=u0.z; dst[3]=u0.w; \
    dst[4]=u1.x; dst[5]=u1.y; dst[6]=u1.z; dst[7]=u1.w; } while(0)

__launch_bounds__(256)
__global__ void scan_kernel(const float* __restrict__ R_, const float* __restrict__ W_,
    const float* __restrict__ K_, const float* __restrict__ V_,
    const float* __restrict__ AT, const float* __restrict__ BTt,
    float* __restrict__ Y, float* __restrict__ S)
{
    __shared__ float4 vbuf[2][88];
    __shared__ float redA[2][8][32];
    __shared__ float redY[2][8][32];
    int bid = blockIdx.x;
    int b = bid >> 5; int rem = bid & 31; int h = rem >> 1; int half = rem & 1;
    int tid = threadIdx.x;
    int kg = tid >> 5, vl = tid & 31;
    int kb = kg * 8;

    const float* msrc = nullptr;
    if (tid < 88) {
        const float* bp; int inner;
        if (tid < 80) {
            int arr = tid / 16, q = tid % 16;
            bp = (arr==0) ? AT : (arr==1) ? W_ : (arr==2) ? BTt : (arr==3) ? K_ : R_;
            inner = q * 4;
        } else {
            bp = V_; inner = half*32 + (tid - 80) * 4;
        }
        msrc = bp + h*HS_ + inner;
    }

    float s[8];
    #pragma unroll
    for (int i = 0; i < 8; i++) s[i] = 0.f;
    float yprev = 0.f;

    size_t row0 = (size_t)b * T_ * D_;
    const size_t yofs = row0 + h*HS_ + half*32 + vl;
    if (tid < 88) vbuf[0][tid] = *(const float4*)(msrc + row0);
    __syncthreads();

    for (int t = 0; t < T_; t++) {
        const int cb = t & 1;
        if (tid < 88 && t + 1 < T_)
            vbuf[cb^1][tid] = *(const float4*)(msrc + row0 + (size_t)(t+1) * D_);

        const float* base = (const float*)vbuf[cb];
        float atr[8], wr[8], btr[8], kr[8], rr[8];
        LOAD8(atr, base       + kb); LOAD8(wr, base +  64 + kb); LOAD8(btr, base + 128 + kb);
        LOAD8(kr,  base + 192 + kb); LOAD8(rr, base + 256 + kb);
        float vt = base[320 + vl];

        float p = 0.f;
        #pragma unroll
        for (int i = 0; i < 8; i++) p += s[i] * atr[i];
        redA[cb][kg][vl] = p;
        redY[cb][kg][vl] = yprev;          // partial y of step t-1
        __syncthreads();

        float sa = 0.f;
        #pragma unroll
        for (int g2 = 0; g2 < 8; g2++) sa += redA[cb][g2][vl];

        if (kg == 0 && t > 0) {
            float yy = 0.f;
            #pragma unroll
            for (int g2 = 0; g2 < 8; g2++) yy += redY[cb][g2][vl];
            Y[yofs + (size_t)(t-1)*D_] = yy;
        }

        float y = 0.f;
        #pragma unroll
        for (int i = 0; i < 8; i++) {
            float sn = s[i]*wr[i] + sa*btr[i] + vt*kr[i];
            s[i] = sn;
            y += sn * rr[i];
        }
        yprev = y;
    }
    // flush final y (t = T-1)
    redY[0][kg][vl] = yprev;
    __syncthreads();
    if (kg == 0) {
        float yy = 0.f;
        #pragma unroll
        for (int g2 = 0; g2 < 8; g2++) yy += redY[0][g2][vl];
        Y[yofs + (size_t)(T_-1)*D_] = yy;
    }

    int v = half*32 + vl;
    size_t sb2 = ((size_t)(b*H_ + h)*HS_ + v)*HS_ + kb;
    *(float4*)(S + sb2)     = make_float4(s[0], s[1], s[2], s[3]);
    *(float4*)(S + sb2 + 4) = make_float4(s[4], s[5], s[6], s[7]);
}

// ---------------- groupnorm + residual + gate + bf16 split ----------------
__launch_bounds__(512)
__global__ void gn_kernel(const float* __restrict__ Y, const float* __restrict__ V_,
    const float* __restrict__ G_, const float* __restrict__ RKS,
    const float* __restrict__ gsc, const float* __restrict__ gbi)
{
    int bt = blockIdx.x;
    int h = threadIdx.x >> 5, lane = threadIdx.x & 31;
    int base = bt * D_ + h * HS_;
    int i0 = base + lane, i1 = i0 + 32;
    int ce0 = h*HS_ + lane, ce1 = ce0 + 32;
    float y0 = Y[i0], y1 = Y[i1];
    float sm = y0 + y1, sq = y0*y0 + y1*y1;
    #pragma unroll
    for (int o = 16; o; o >>= 1) {
        sm += __shfl_xor_sync(0xffffffffu, sm, o);
        sq += __shfl_xor_sync(0xffffffffu, sq, o);
    }
    float mu  = sm * (1.f/64.f);
    float var = sq * (1.f/64.f) - mu*mu;
    float inv = rsqrtf(var + 1e-5f);
    float rk  = RKS[bt*H_ + h];
    float o0 = ((y0 - mu)*inv*gsc[ce0] + gbi[ce0] + rk*V_[i0]) * G_[i0];
    float o1 = ((y1 - mu)*inv*gsc[ce1] + gbi[ce1] + rk*V_[i1]) * G_[i1];
    __nv_bfloat16 h0,l0,h1,l1;
    split_bf(o0, h0, l0); split_bf(o1, h1, l1);
    g_zhi[i0] = h0; g_zhi[i1] = h1;
    g_zlo[i0] = l0; g_zlo[i1] = l1;
}

// ---------------- launch ----------------
extern "C" void kernel_launch(void* const* d_in, const int* in_sizes, int n_in,
                              void* d_out, int out_size)
{
    const float* cur    = (const float*)d_in[0];
    const float* prev   = (const float*)d_in[1];
    const float* vfirst = (const float*)d_in[2];
    const float* lam    = (const float*)d_in[3];
    const float* rw_W   = (const float*)d_in[4];
    const float* w1     = (const float*)d_in[5];
    const float* w2     = (const float*)d_in[6];
    const float* w2b    = (const float*)d_in[7];
    const float* kw     = (const float*)d_in[8];
    const float* vw     = (const float*)d_in[9];
    const float* a1     = (const float*)d_in[10];
    const float* a2     = (const float*)d_in[11];
    const float* a2b    = (const float*)d_in[12];
    const float* v1     = (const float*)d_in[13];
    const float* v2     = (const float*)d_in[14];
    const float* v2b    = (const float*)d_in[15];
    const float* g1     = (const float*)d_in[16];
    const float* g2     = (const float*)d_in[17];
    const float* g2b    = (const float*)d_in[18];
    const float* k_k    = (const float*)d_in[19];
    const float* k_a    = (const float*)d_in[20];
    const float* r_k    = (const float*)d_in[21];
    const float* gsc    = (const float*)d_in[22];
    const float* gbi    = (const float*)d_in[23];
    const float* outW   = (const float*)d_in[24];
    (void)in_sizes; (void)n_in;

    float *pr,*pwl,*pk,*pv,*pa,*pg,*pat,*pbt,*phv,*prks,*py,*pds;
    cudaGetSymbolAddress((void**)&pr,  g_r);
    cudaGetSymbolAddress((void**)&pwl, g_wl);
    cudaGetSymbolAddress((void**)&pk,  g_k);
    cudaGetSymbolAddress((void**)&pv,  g_v);
    cudaGetSymbolAddress((void**)&pa,  g_a);
    cudaGetSymbolAddress((void**)&pg,  g_g);
    cudaGetSymbolAddress((void**)&pat, g_at);
    cudaGetSymbolAddress((void**)&pbt, g_bt);
    cudaGetSymbolAddress((void**)&phv, g_hv);
    cudaGetSymbolAddress((void**)&prks,g_rks);
    cudaGetSymbolAddress((void**)&py,  g_y);
    cudaGetSymbolAddress((void**)&pds, g_ds);

    __nv_bfloat16 *pwhiT,*pwloT,*pahi,*palo,*pzhi,*pzlo,*pl1h,*pl1l,*pl2h,*pl2l,*ps1h,*ps1l;
    cudaGetSymbolAddress((void**)&pwhiT, g_whiT);
    cudaGetSymbolAddress((void**)&pwloT, g_wloT);
    cudaGetSymbolAddress((void**)&pahi,  g_ahi);
    cudaGetSymbolAddress((void**)&palo,  g_alo);
    cudaGetSymbolAddress((void**)&pzhi,  g_zhi);
    cudaGetSymbolAddress((void**)&pzlo,  g_zlo);
    cudaGetSymbolAddress((void**)&pl1h,  g_l1hi);
    cudaGetSymbolAddress((void**)&pl1l,  g_l1lo);
    cudaGetSymbolAddress((void**)&pl2h,  g_l2hi);
    cudaGetSymbolAddress((void**)&pl2l,  g_l2lo);
    cudaGetSymbolAddress((void**)&ps1h,  g_s1hi);
    cudaGetSymbolAddress((void**)&ps1l,  g_s1lo);

    float* out = (float*)d_out;
    const int YN = BT_*D_;
    const int SN = B_*H_*HS_*HS_;
    float* stateOut = (out_size >= YN + SN) ? (out + YN) : pds;

    cudaFuncSetAttribute(mma_gemm,  cudaFuncAttributeMaxDynamicSharedMemorySize, MMA_SMEM_BYTES);
    cudaFuncSetAttribute(mma_lora1, cudaFuncAttributeMaxDynamicSharedMemorySize, L_SMEM_BYTES);

    const size_t O_W1 = 0, O_A1 = 64*1024, O_V1 = 128*1024, O_G1 = 192*1024;
    const size_t P_W2 = 0, P_A2 = 1024*64, P_V2 = 2*1024*64, P_G2 = 3*1024*64;
    const size_t S_HW = 0, S_HA = (size_t)BT_*64, S_HV = (size_t)BT_*128, S_HG = (size_t)BT_*192;

    TSParams TP;
    TP.j[0]  = { rw_W, 1024, 1024, pwhiT + 0*1024*1024, pwloT + 0*1024*1024, 1024 };
    TP.j[1]  = { kw,   1024, 1024, pwhiT + 1*1024*1024, pwloT + 1*1024*1024, 1024 };
    TP.j[2]  = { vw,   1024, 1024, pwhiT + 2*1024*1024, pwloT + 2*1024*1024, 1024 };
    TP.j[3]  = { outW, 1024, 1024, pwhiT + 3*1024*1024, pwloT + 3*1024*1024, 1024 };
    TP.j[4]  = { w1, 1024,  64, pl1h + O_W1, pl1l + O_W1, 1024 };
    TP.j[5]  = { a1, 1024,  64, pl1h + O_A1, pl1l + O_A1, 1024 };
    TP.j[6]  = { v1, 1024,  32, pl1h + O_V1, pl1l + O_V1, 1024 };
    TP.j[7]  = { g1, 1024, 128, pl1h + O_G1, pl1l + O_G1, 1024 };
    TP.j[8]  = { w2,  64, 1024, pl2h + P_W2, pl2l + P_W2,  64 };
    TP.j[9]  = { a2,  64, 1024, pl2h + P_A2, pl2l + P_A2,  64 };
    TP.j[10] = { v2,  32, 1024, pl2h + P_V2, pl2l + P_V2,  64 };
    TP.j[11] = { g2, 128, 1024, pl2h + P_G2, pl2l + P_G2, 128 };
    tsplit_kernel<<<dim3(32,32,12), 256>>>(TP);
    asplit_kernel<<<dim3(4096,6),   256>>>(cur, prev, lam);

    MParams Prkv;
    {
        const int br[3] = {0, 2, 3};
        float* cs[3] = {pr, pk, pv};
        for (int z = 0; z < 3; z++) {
            Prkv.s[z] = { pahi + (size_t)br[z]*BT_*D_, palo + (size_t)br[z]*BT_*D_,
                          pwhiT + (size_t)z*1024*1024, pwloT + (size_t)z*1024*1024,
                          1024, 1024, 1024, nullptr, 0, cs[z] };
        }
        Prkv.s[3] = Prkv.s[0];
    }
    mma_gemm<<<dim3(8,32,3), 256, MMA_SMEM_BYTES>>>(Prkv);

    LParams LP;
    LP.s[0] = { pahi + (size_t)1*BT_*D_, palo + (size_t)1*BT_*D_, pl1h+O_W1, pl1l+O_W1, 1, ps1h+S_HW, ps1l+S_HW,  64, 0 };
    LP.s[1] = { pahi + (size_t)4*BT_*D_, palo + (size_t)4*BT_*D_, pl1h+O_A1, pl1l+O_A1, 0, ps1h+S_HA, ps1l+S_HA,  64, 0 };
    LP.s[2] = { pahi + (size_t)3*BT_*D_, palo + (size_t)3*BT_*D_, pl1h+O_V1, pl1l+O_V1, 0, ps1h+S_HV, ps1l+S_HV,  64, 0 };
    LP.s[3] = { pahi + (size_t)5*BT_*D_, palo + (size_t)5*BT_*D_, pl1h+O_G1,         pl1l+O_G1,         2, ps1h+S_HG, ps1l+S_HG, 128, 0 };
    LP.s[4] = { pahi + (size_t)5*BT_*D_, palo + (size_t)5*BT_*D_, pl1h+O_G1+64*1024, pl1l+O_G1+64*1024, 2, ps1h+S_HG, ps1l+S_HG, 128, 64 };
    mma_lora1<<<dim3(1,64,5), 128, L_SMEM_BYTES>>>(LP);

    MParams P2;
    P2.s[0] = { ps1h+S_HW, ps1l+S_HW, pl2h+P_W2, pl2l+P_W2,  64,  64,  64, w2b, 0, pwl };
    P2.s[1] = { ps1h+S_HA, ps1l+S_HA, pl2h+P_A2, pl2l+P_A2,  64,  64,  64, a2b, 2, pa  };
    P2.s[2] = { ps1h+S_HV, ps1l+S_HV, pl2h+P_V2, pl2l+P_V2,  64,  64,  64, v2b, 2, phv };
    P2.s[3] = { ps1h+S_HG, ps1l+S_HG, pl2h+P_G2, pl2l+P_G2, 128, 128, 128, g2b, 0, pg  };
    mma_gemm<<<dim3(8,32,4), 256, MMA_SMEM_BYTES>>>(P2);

    post_kernel<<<BT_, 512>>>(pk, pv, pwl, pa, pr, phv, vfirst, k_k, k_a, r_k, pat, pbt, prks);
    scan_kernel<<<128, 256>>>(pr, pwl, pk, pv, pat, pbt, py, stateOut);
    gn_kernel  <<<BT_, 512>>>(py, pv, pg, prks, gsc, gbi);

    MParams Pout;
    Pout.s[0] = { pzhi, pzlo, pwhiT + (size_t)3*1024*1024, pwloT + (size_t)3*1024*1024,
                  1024, 1024, 1024, nullptr, 0, out };
    Pout.s[1] = Pout.s[0]; Pout.s[2] = Pout.s[0]; Pout.s[3] = Pout.s[0];
    mma_gemm<<<dim3(8,32,1), 256, MMA_SMEM_BYTES>>>(Pout);

    if (out_size >= YN + SN + YN)
        cudaMemcpyAsync(out + YN + SN, vfirst, (size_t)YN*sizeof(float),
                        cudaMemcpyDeviceToDevice, 0);
}